// round 2
// baseline (speedup 1.0000x reference)
#include <cuda_runtime.h>
#include <math.h>

#define Bn 64
#define Sn 512
#define Hn 1024
#define En 128
#define Ln 49
#define G3 3072            // 3*H
#define IW 1152            // E+H
#define NEGV (-1e12f)

#define NCTA 128
#define TPB  256
// dynamic smem for scan: w_sm 24*1024 + h_sm 64*132 + gh_sm 64*24 floats
#define SCAN_SMEM ((24*1024 + 64*132 + 64*24) * 4)

// ---------------- device scratch (no allocations allowed) ----------------
__device__ __align__(16) float g_gx[(size_t)Bn * Sn * G3];     // [t][b][3H]  (~402 MB)
__device__ __align__(16) float g_outs[(size_t)Bn * Sn * Hn];   // [b][t][H]   (~134 MB)
__device__ __align__(16) float g_lt[Ln * G3];                  // label gate table (incl b_ih)
__device__ __align__(16) float g_h[2][Bn * Hn];                // ping-pong hidden state
__device__ unsigned g_bar_count;
__device__ unsigned g_bar_gen;

// ---------------- grid barrier for persistent scan kernel ----------------
__device__ __forceinline__ void gbar() {
    __threadfence();
    __syncthreads();
    if (threadIdx.x == 0) {
        unsigned gen = *((volatile unsigned*)&g_bar_gen);
        unsigned old = atomicAdd(&g_bar_count, 1u);
        if (old == NCTA - 1) {
            g_bar_count = 0;
            __threadfence();
            atomicExch(&g_bar_gen, gen + 1u);
        } else {
            while (*((volatile unsigned*)&g_bar_gen) == gen) {}
            __threadfence();
        }
    }
    __syncthreads();
}

// ---------------- IOBES transition mask ----------------
// labels: 0='O'; i>0: prefix p=(i-1)&3 (0:B 1:I 2:E 3:S), type=(i-1)>>2
__device__ __forceinline__ bool allowf(int prev, int nxt) {
    if (prev == 0 || ((prev - 1) & 3) >= 2) {       // O, E-*, S-*
        if (nxt == 0) return true;
        int np = (nxt - 1) & 3;
        return (np == 0) || (np == 3);               // B-* or S-*
    } else {                                         // B-* or I-*
        if (nxt == 0) return false;
        int np = (nxt - 1) & 3;
        return (((nxt - 1) >> 2) == ((prev - 1) >> 2)) && (np == 1 || np == 2);
    }
}

__device__ __forceinline__ int clamp_lab(int v) {
    return v < 0 ? 0 : (v > Ln - 1 ? Ln - 1 : v);
}

// ---------------- kernel 1: label gate table ----------------
// lt[l][g] = b_ih[g] + sum_e emb[l][e] * w_ih[g][e]
__global__ void k_lt(const float* __restrict__ emb,
                     const float* __restrict__ w_ih,
                     const float* __restrict__ b_ih) {
    int l = blockIdx.y;
    int g = blockIdx.x * 128 + threadIdx.x;
    __shared__ float es[En];
    if (threadIdx.x < En) es[threadIdx.x] = emb[l * En + threadIdx.x];
    __syncthreads();
    float acc = b_ih[g];
    const float* w = w_ih + (size_t)g * IW;
#pragma unroll 8
    for (int e = 0; e < En; e++) acc = fmaf(es[e], w[e], acc);
    g_lt[l * G3 + g] = acc;
}

// ---------------- kernel 2: gx = word_emb @ w_ih[:,E:]^T + lt[prev] ------
// M rows ordered t-major: row = t*64 + b  (one tile == one t)
__global__ void __launch_bounds__(256) k_gx(const float* __restrict__ we,
                                            const int* __restrict__ lab,
                                            const float* __restrict__ w_ih) {
    __shared__ float a_sm[16][68];   // [k][b]
    __shared__ float b_sm[16][64];   // [k][g_local]
    int t  = blockIdx.y;
    int g0 = blockIdx.x * 64;
    int tid = threadIdx.x;

    int ar = tid >> 2, akq = tid & 3;     // A loader
    int bg = tid & 63, bkq = tid >> 6;    // B loader
    const float* aptr = we + (size_t)ar * (Sn * Hn) + (size_t)t * Hn + akq * 4;
    const float* bptr = w_ih + (size_t)(g0 + bg) * IW + En + bkq * 4;
    int ty = tid >> 4, tx = tid & 15;

    float acc[4][4];
#pragma unroll
    for (int q = 0; q < 4; q++)
#pragma unroll
        for (int p = 0; p < 4; p++) acc[q][p] = 0.f;

    float4 av = *(const float4*)(aptr);
    float4 bv = *(const float4*)(bptr);

    for (int k0 = 0; k0 < Hn; k0 += 16) {
        a_sm[akq * 4 + 0][ar] = av.x;
        a_sm[akq * 4 + 1][ar] = av.y;
        a_sm[akq * 4 + 2][ar] = av.z;
        a_sm[akq * 4 + 3][ar] = av.w;
        b_sm[bkq * 4 + 0][bg] = bv.x;
        b_sm[bkq * 4 + 1][bg] = bv.y;
        b_sm[bkq * 4 + 2][bg] = bv.z;
        b_sm[bkq * 4 + 3][bg] = bv.w;
        __syncthreads();
        if (k0 + 16 < Hn) {
            av = *(const float4*)(aptr + k0 + 16);
            bv = *(const float4*)(bptr + k0 + 16);
        }
#pragma unroll
        for (int kk = 0; kk < 16; kk++) {
            float4 a4 = *(const float4*)&a_sm[kk][ty * 4];
            float4 b4 = *(const float4*)&b_sm[kk][tx * 4];
            acc[0][0] = fmaf(a4.x, b4.x, acc[0][0]);
            acc[0][1] = fmaf(a4.x, b4.y, acc[0][1]);
            acc[0][2] = fmaf(a4.x, b4.z, acc[0][2]);
            acc[0][3] = fmaf(a4.x, b4.w, acc[0][3]);
            acc[1][0] = fmaf(a4.y, b4.x, acc[1][0]);
            acc[1][1] = fmaf(a4.y, b4.y, acc[1][1]);
            acc[1][2] = fmaf(a4.y, b4.z, acc[1][2]);
            acc[1][3] = fmaf(a4.y, b4.w, acc[1][3]);
            acc[2][0] = fmaf(a4.z, b4.x, acc[2][0]);
            acc[2][1] = fmaf(a4.z, b4.y, acc[2][1]);
            acc[2][2] = fmaf(a4.z, b4.z, acc[2][2]);
            acc[2][3] = fmaf(a4.z, b4.w, acc[2][3]);
            acc[3][0] = fmaf(a4.w, b4.x, acc[3][0]);
            acc[3][1] = fmaf(a4.w, b4.y, acc[3][1]);
            acc[3][2] = fmaf(a4.w, b4.z, acc[3][2]);
            acc[3][3] = fmaf(a4.w, b4.w, acc[3][3]);
        }
        __syncthreads();
    }

#pragma unroll
    for (int q = 0; q < 4; q++) {
        int b = ty * 4 + q;
        int prev = (t == 0) ? 0 : clamp_lab(lab[b * Sn + t - 1]);
        const float* ltp = g_lt + (size_t)prev * G3 + g0 + tx * 4;
        float4 o;
        o.x = acc[q][0] + ltp[0];
        o.y = acc[q][1] + ltp[1];
        o.z = acc[q][2] + ltp[2];
        o.w = acc[q][3] + ltp[3];
        *(float4*)(g_gx + (size_t)t * (Bn * G3) + (size_t)b * G3 + g0 + tx * 4) = o;
    }
}

// ---------------- kernel 3: persistent GRU scan ----------------
// CTA `cta` owns h-columns [cta*8, cta*8+8); computes gates r,z,n for them.
__global__ void __launch_bounds__(TPB, 1) k_scan(const float* __restrict__ w_hh,
                                                 const float* __restrict__ b_hh) {
    extern __shared__ float sm[];
    float* w_sm  = sm;                       // [24][1024]
    float* h_sm  = sm + 24 * 1024;           // [64][132]
    float* gh_sm = h_sm + 64 * 132;          // [64][24]
    __shared__ float bhh_s[24];

    int cta = blockIdx.x;
    int tid = threadIdx.x;
    int c0  = cta * 8;

    // cache weight slice: j in [0,24): gate j>>3, hcol c0 + (j&7)
    for (int idx = tid; idx < 24 * 1024; idx += TPB) {
        int j = idx >> 10, k = idx & 1023;
        int wrow = (j >> 3) * Hn + c0 + (j & 7);
        w_sm[idx] = w_hh[(size_t)wrow * Hn + k];
    }
    if (tid < 24) bhh_s[tid] = b_hh[(tid >> 3) * Hn + c0 + (tid & 7)];

    // zero initial hidden state
    for (int idx = cta * TPB + tid; idx < Bn * Hn; idx += NCTA * TPB)
        g_h[0][idx] = 0.f;
    gbar();

    int i0 = tid & 31, i1 = i0 + 32;
    int j0 = (tid >> 5) * 3;

    for (int t = 0; t < Sn; t++) {
        const float* hp  = g_h[t & 1];
        float*       hnx = g_h[(t + 1) & 1];
        float acc[6] = {0.f, 0.f, 0.f, 0.f, 0.f, 0.f};

        for (int kc = 0; kc < 8; kc++) {
            // stage h chunk [64][128] into smem (padded 132)
#pragma unroll
            for (int q = 0; q < 8; q++) {
                int lin = tid + q * TPB;            // float4 index
                int r = lin >> 5, kk = (lin & 31) << 2;
                float4 v = *(const float4*)(hp + (size_t)r * Hn + kc * 128 + kk);
                *(float4*)(h_sm + r * 132 + kk) = v;
            }
            __syncthreads();
            const float* wbase = w_sm + kc * 128;
#pragma unroll 8
            for (int kq = 0; kq < 32; kq++) {
                int kk = kq << 2;
                float4 ha = *(const float4*)(h_sm + i0 * 132 + kk);
                float4 hb = *(const float4*)(h_sm + i1 * 132 + kk);
                float4 w0 = *(const float4*)(wbase + (j0 + 0) * 1024 + kk);
                float4 w1 = *(const float4*)(wbase + (j0 + 1) * 1024 + kk);
                float4 w2 = *(const float4*)(wbase + (j0 + 2) * 1024 + kk);
                acc[0] = fmaf(ha.x, w0.x, acc[0]); acc[0] = fmaf(ha.y, w0.y, acc[0]);
                acc[0] = fmaf(ha.z, w0.z, acc[0]); acc[0] = fmaf(ha.w, w0.w, acc[0]);
                acc[1] = fmaf(ha.x, w1.x, acc[1]); acc[1] = fmaf(ha.y, w1.y, acc[1]);
                acc[1] = fmaf(ha.z, w1.z, acc[1]); acc[1] = fmaf(ha.w, w1.w, acc[1]);
                acc[2] = fmaf(ha.x, w2.x, acc[2]); acc[2] = fmaf(ha.y, w2.y, acc[2]);
                acc[2] = fmaf(ha.z, w2.z, acc[2]); acc[2] = fmaf(ha.w, w2.w, acc[2]);
                acc[3] = fmaf(hb.x, w0.x, acc[3]); acc[3] = fmaf(hb.y, w0.y, acc[3]);
                acc[3] = fmaf(hb.z, w0.z, acc[3]); acc[3] = fmaf(hb.w, w0.w, acc[3]);
                acc[4] = fmaf(hb.x, w1.x, acc[4]); acc[4] = fmaf(hb.y, w1.y, acc[4]);
                acc[4] = fmaf(hb.z, w1.z, acc[4]); acc[4] = fmaf(hb.w, w1.w, acc[4]);
                acc[5] = fmaf(hb.x, w2.x, acc[5]); acc[5] = fmaf(hb.y, w2.y, acc[5]);
                acc[5] = fmaf(hb.z, w2.z, acc[5]); acc[5] = fmaf(hb.w, w2.w, acc[5]);
            }
            __syncthreads();
        }

        gh_sm[i0 * 24 + j0 + 0] = acc[0];
        gh_sm[i0 * 24 + j0 + 1] = acc[1];
        gh_sm[i0 * 24 + j0 + 2] = acc[2];
        gh_sm[i1 * 24 + j0 + 0] = acc[3];
        gh_sm[i1 * 24 + j0 + 1] = acc[4];
        gh_sm[i1 * 24 + j0 + 2] = acc[5];
        __syncthreads();

        // combine: 64 batches x 8 cols = 512 tasks
        const float* gxt = g_gx + (size_t)t * (Bn * G3);
#pragma unroll
        for (int q = 0; q < 2; q++) {
            int task = tid + q * TPB;
            int i = task >> 3, c = task & 7;
            int gc = c0 + c;
            float ghr = gh_sm[i * 24 + c]      + bhh_s[c];
            float ghz = gh_sm[i * 24 + 8 + c]  + bhh_s[8 + c];
            float ghn = gh_sm[i * 24 + 16 + c] + bhh_s[16 + c];
            const float* gxr = gxt + (size_t)i * G3 + gc;
            float r = 1.f / (1.f + expf(-(gxr[0]    + ghr)));
            float z = 1.f / (1.f + expf(-(gxr[1024] + ghz)));
            float n = tanhf(gxr[2048] + r * ghn);
            float hprev = hp[i * Hn + gc];
            float hnew = (1.f - z) * n + z * hprev;
            hnx[i * Hn + gc] = hnew;
            g_outs[(size_t)i * (Sn * Hn) + (size_t)t * Hn + gc] = hnew;
        }
        gbar();
    }
}

// ---------------- kernel 4: logits + IOBES mask ----------------
// rows = b*512 + t (matches g_outs layout); 64 rows x 64 cols (49 valid)
__global__ void __launch_bounds__(256) k_logits(const int* __restrict__ lab,
                                                const float* __restrict__ w_out,
                                                const float* __restrict__ b_out,
                                                float* __restrict__ out) {
    __shared__ float a_sm[16][68];
    __shared__ float b_sm[16][64];
    int m0 = blockIdx.x * 64;
    int tid = threadIdx.x;

    int ar = tid >> 2, akq = tid & 3;
    int bl = tid & 63, bkq = tid >> 6;
    const float* aptr = g_outs + (size_t)(m0 + ar) * Hn + akq * 4;
    int ty = tid >> 4, tx = tid & 15;

    float acc[4][4];
#pragma unroll
    for (int q = 0; q < 4; q++)
#pragma unroll
        for (int p = 0; p < 4; p++) acc[q][p] = 0.f;

    float4 av = *(const float4*)(aptr);
    float4 bv = make_float4(0.f, 0.f, 0.f, 0.f);
    if (bl < Ln) bv = *(const float4*)(w_out + (size_t)bl * Hn + bkq * 4);

    for (int k0 = 0; k0 < Hn; k0 += 16) {
        a_sm[akq * 4 + 0][ar] = av.x;
        a_sm[akq * 4 + 1][ar] = av.y;
        a_sm[akq * 4 + 2][ar] = av.z;
        a_sm[akq * 4 + 3][ar] = av.w;
        b_sm[bkq * 4 + 0][bl] = bv.x;
        b_sm[bkq * 4 + 1][bl] = bv.y;
        b_sm[bkq * 4 + 2][bl] = bv.z;
        b_sm[bkq * 4 + 3][bl] = bv.w;
        __syncthreads();
        if (k0 + 16 < Hn) {
            av = *(const float4*)(aptr + k0 + 16);
            if (bl < Ln) bv = *(const float4*)(w_out + (size_t)bl * Hn + bkq * 4 + k0 + 16);
        }
#pragma unroll
        for (int kk = 0; kk < 16; kk++) {
            float4 a4 = *(const float4*)&a_sm[kk][ty * 4];
            float4 b4 = *(const float4*)&b_sm[kk][tx * 4];
#pragma unroll
            for (int q = 0; q < 4; q++) {
                float aval = (q == 0) ? a4.x : (q == 1) ? a4.y : (q == 2) ? a4.z : a4.w;
                acc[q][0] = fmaf(aval, b4.x, acc[q][0]);
                acc[q][1] = fmaf(aval, b4.y, acc[q][1]);
                acc[q][2] = fmaf(aval, b4.z, acc[q][2]);
                acc[q][3] = fmaf(aval, b4.w, acc[q][3]);
            }
        }
        __syncthreads();
    }

#pragma unroll
    for (int q = 0; q < 4; q++) {
        int row = m0 + ty * 4 + q;
        int b = row >> 9, t = row & 511;
        int prev = (t == 0) ? 0 : clamp_lab(lab[b * Sn + t - 1]);
#pragma unroll
        for (int p = 0; p < 4; p++) {
            int l = tx * 4 + p;
            if (l < Ln) {
                float v = allowf(prev, l) ? (acc[q][p] + b_out[l]) : NEGV;
                out[(size_t)row * Ln + l] = v;
            }
        }
    }
}

// ---------------- launcher ----------------
extern "C" void kernel_launch(void* const* d_in, const int* in_sizes, int n_in,
                              void* d_out, int out_size) {
    // Resolve inputs by element count (robust to metadata ordering).
    const float* we    = nullptr;   // 64*512*1024 = 33554432
    const int*   lab   = nullptr;   // 64*512      = 32768
    const float* emb   = nullptr;   // 49*128      = 6272
    const float* w_ih  = nullptr;   // 3072*1152   = 3538944
    const float* w_hh  = nullptr;   // 3072*1024   = 3145728
    const float* b_ih  = nullptr;   // 3072 (first)
    const float* b_hh  = nullptr;   // 3072 (second)
    const float* w_out = nullptr;   // 49*1024     = 50176
    const float* b_out = nullptr;   // 49

    for (int i = 0; i < n_in; i++) {
        int n = in_sizes[i];
        const void* p = d_in[i];
        switch (n) {
            case 33554432: we    = (const float*)p; break;
            case 32768:    lab   = (const int*)p;   break;
            case 6272:     emb   = (const float*)p; break;
            case 3538944:  w_ih  = (const float*)p; break;
            case 3145728:  w_hh  = (const float*)p; break;
            case 50176:    w_out = (const float*)p; break;
            case 49:       b_out = (const float*)p; break;
            case 3072:
                if (!b_ih) b_ih = (const float*)p; else b_hh = (const float*)p;
                break;
            default: break;
        }
    }
    float* out = (float*)d_out;

    cudaFuncSetAttribute(k_scan, cudaFuncAttributeMaxDynamicSharedMemorySize, SCAN_SMEM);

    k_lt    <<<dim3(24, Ln), 128>>>(emb, w_ih, b_ih);
    k_gx    <<<dim3(48, Sn), 256>>>(we, lab, w_ih);
    k_scan  <<<NCTA, TPB, SCAN_SMEM>>>(w_hh, b_hh);
    k_logits<<<Bn * Sn / 64, 256>>>(lab, w_out, b_out, out);
}

// round 4
// speedup vs baseline: 1.3554x; 1.3554x over previous
#include <cuda_runtime.h>
#include <cuda_bf16.h>
#include <math.h>

#define Bn 64
#define Sn 512
#define Hn 1024
#define En 128
#define Ln 49
#define G3 3072            // 3*H
#define IW 1152            // E+H
#define NEGV (-1e12f)

#define NCTA 128
#define TPB  256
#define SCAN_SMEM ((24*1024 + 64*132 + 64*24) * 4)

// k_gx_mma: 128x128 CTA tile, K staged 64 wide, double buffered
#define GX_SMEM (2 * 2 * 128 * 64 * 2)   // 2 stages x (A,B) x 128 rows x 64 bf16 = 65536

// ---------------- device scratch ----------------
__device__ __align__(16) float g_gx[(size_t)Bn * Sn * G3];     // [t][b][3H]
__device__ __align__(16) float g_outs[(size_t)Bn * Sn * Hn];   // [b][t][H]
__device__ __align__(16) float g_lt[Ln * G3];
__device__ __align__(16) float g_h[2][Bn * Hn];
__device__ __align__(16) uint4 g_abf[(size_t)Bn * Sn * 128];   // bf16 A [m=t*64+b][1024]
__device__ __align__(16) uint4 g_bbf[(size_t)G3 * 128];        // bf16 B [g][1024]
__device__ unsigned g_bar_count;
__device__ unsigned g_bar_gen;

// ---------------- PTX helpers ----------------
__device__ __forceinline__ unsigned smem_u32(const void* p) {
    unsigned a;
    asm("{ .reg .u64 t; cvta.to.shared.u64 t, %1; cvt.u32.u64 %0, t; }" : "=r"(a) : "l"(p));
    return a;
}
__device__ __forceinline__ void ldsm_x4(unsigned* r, unsigned addr) {
    asm volatile("ldmatrix.sync.aligned.m8n8.x4.shared.b16 {%0,%1,%2,%3}, [%4];"
                 : "=r"(r[0]), "=r"(r[1]), "=r"(r[2]), "=r"(r[3]) : "r"(addr));
}
__device__ __forceinline__ void ldsm_x2(unsigned* r, unsigned addr) {
    asm volatile("ldmatrix.sync.aligned.m8n8.x2.shared.b16 {%0,%1}, [%2];"
                 : "=r"(r[0]), "=r"(r[1]) : "r"(addr));
}
__device__ __forceinline__ void mma_bf16(float* c, const unsigned* a, const unsigned* b) {
    asm volatile(
        "mma.sync.aligned.m16n8k16.row.col.f32.bf16.bf16.f32 "
        "{%0,%1,%2,%3}, {%4,%5,%6,%7}, {%8,%9}, {%0,%1,%2,%3};"
        : "+f"(c[0]), "+f"(c[1]), "+f"(c[2]), "+f"(c[3])
        : "r"(a[0]), "r"(a[1]), "r"(a[2]), "r"(a[3]), "r"(b[0]), "r"(b[1]));
}
// packed fp32x2 FMA (plain sm_100+ feature, compiles on this target)
__device__ __forceinline__ unsigned long long ffma2(unsigned long long a,
                                                    unsigned long long b,
                                                    unsigned long long c) {
    unsigned long long d;
    asm("fma.rn.f32x2 %0, %1, %2, %3;" : "=l"(d) : "l"(a), "l"(b), "l"(c));
    return d;
}
__device__ __forceinline__ float f2sum(unsigned long long v) {
    float lo, hi;
    asm("mov.b64 {%0, %1}, %2;" : "=f"(lo), "=f"(hi) : "l"(v));
    return lo + hi;
}

// ---------------- grid barrier ----------------
__device__ __forceinline__ void gbar() {
    __threadfence();
    __syncthreads();
    if (threadIdx.x == 0) {
        unsigned gen = *((volatile unsigned*)&g_bar_gen);
        unsigned old = atomicAdd(&g_bar_count, 1u);
        if (old == NCTA - 1) {
            g_bar_count = 0;
            __threadfence();
            atomicExch(&g_bar_gen, gen + 1u);
        } else {
            while (*((volatile unsigned*)&g_bar_gen) == gen) {}
            __threadfence();
        }
    }
    __syncthreads();
}

// ---------------- IOBES ----------------
__device__ __forceinline__ bool allowf(int prev, int nxt) {
    if (prev == 0 || ((prev - 1) & 3) >= 2) {
        if (nxt == 0) return true;
        int np = (nxt - 1) & 3;
        return (np == 0) || (np == 3);
    } else {
        if (nxt == 0) return false;
        int np = (nxt - 1) & 3;
        return (((nxt - 1) >> 2) == ((prev - 1) >> 2)) && (np == 1 || np == 2);
    }
}
__device__ __forceinline__ int clamp_lab(int v) {
    return v < 0 ? 0 : (v > Ln - 1 ? Ln - 1 : v);
}

// ---------------- k_lt ----------------
__global__ void k_lt(const float* __restrict__ emb,
                     const float* __restrict__ w_ih,
                     const float* __restrict__ b_ih) {
    int l = blockIdx.y;
    int g = blockIdx.x * 128 + threadIdx.x;
    __shared__ float es[En];
    if (threadIdx.x < En) es[threadIdx.x] = emb[l * En + threadIdx.x];
    __syncthreads();
    float acc = b_ih[g];
    const float* w = w_ih + (size_t)g * IW;
#pragma unroll 8
    for (int e = 0; e < En; e++) acc = fmaf(es[e], w[e], acc);
    g_lt[l * G3 + g] = acc;
}

// ---------------- bf16 cast kernels ----------------
__device__ __forceinline__ unsigned pk2(float a, float b) {
    __nv_bfloat162 h = __floats2bfloat162_rn(a, b);
    return *(unsigned*)&h;
}
__global__ void k_cast_a(const float* __restrict__ we) {
    size_t c = (size_t)blockIdx.x * 256 + threadIdx.x;
    int m = (int)(c >> 7), kq = (int)(c & 127);
    int t = m >> 6, b = m & 63;
    const float4* src = (const float4*)(we + ((size_t)b * Sn + t) * Hn + kq * 8);
    float4 f0 = src[0], f1 = src[1];
    uint4 o;
    o.x = pk2(f0.x, f0.y); o.y = pk2(f0.z, f0.w);
    o.z = pk2(f1.x, f1.y); o.w = pk2(f1.z, f1.w);
    g_abf[c] = o;
}
__global__ void k_cast_b(const float* __restrict__ w_ih) {
    size_t c = (size_t)blockIdx.x * 256 + threadIdx.x;
    int g = (int)(c >> 7), kq = (int)(c & 127);
    const float4* src = (const float4*)(w_ih + (size_t)g * IW + En + kq * 8);
    float4 f0 = src[0], f1 = src[1];
    uint4 o;
    o.x = pk2(f0.x, f0.y); o.y = pk2(f0.z, f0.w);
    o.z = pk2(f1.x, f1.y); o.w = pk2(f1.z, f1.w);
    g_bbf[c] = o;
}

// ---------------- k_gx_mma: HMMA bf16 GEMM + lt epilogue ------------------
// D[m, n] = sum_k A[m,k] B[n,k];  m = t*64+b rows, n = gate index
// 8 warps: warp (wm in 0..1, wn in 0..3) computes 64x32 of the 128x128 tile.
__global__ void __launch_bounds__(256, 1) k_gx_mma(const int* __restrict__ lab) {
    extern __shared__ char smem[];
    unsigned sb = smem_u32(smem);
    const unsigned aOff[2] = { 0u, 32768u };
    const unsigned bOff[2] = { 16384u, 49152u };

    int tid = threadIdx.x, lane = tid & 31, wid = tid >> 5;
    int wm = wid >> 2, wn = wid & 3;
    int n0 = blockIdx.x * 128;
    int m0 = blockIdx.y * 128;

    float acc[16][4];
#pragma unroll
    for (int i = 0; i < 16; i++)
#pragma unroll
        for (int j = 0; j < 4; j++) acc[i][j] = 0.f;

    uint4 ra[4], rb[4];
#pragma unroll
    for (int q = 0; q < 4; q++) {
        int idx = tid * 4 + q, r = idx >> 3, i = idx & 7;
        ra[q] = g_abf[(size_t)(m0 + r) * 128 + i];
        rb[q] = g_bbf[(size_t)(n0 + r) * 128 + i];
    }

    int il = lane & 15;
    for (int kc = 0; kc < 16; kc++) {
        int s = kc & 1;
#pragma unroll
        for (int q = 0; q < 4; q++) {
            int idx = tid * 4 + q, r = idx >> 3, i = idx & 7;
            unsigned off = (unsigned)(r * 128 + ((i ^ (r & 7)) << 4));
            *(uint4*)(smem + aOff[s] + off) = ra[q];
            *(uint4*)(smem + bOff[s] + off) = rb[q];
        }
        __syncthreads();
        if (kc + 1 < 16) {
#pragma unroll
            for (int q = 0; q < 4; q++) {
                int idx = tid * 4 + q, r = idx >> 3, i = idx & 7;
                ra[q] = g_abf[(size_t)(m0 + r) * 128 + (kc + 1) * 8 + i];
                rb[q] = g_bbf[(size_t)(n0 + r) * 128 + (kc + 1) * 8 + i];
            }
        }
#pragma unroll
        for (int ks = 0; ks < 4; ks++) {
            unsigned afr[4][4], bfr[4][2];
#pragma unroll
            for (int mt = 0; mt < 4; mt++) {
                int row = wm * 64 + mt * 16 + il;
                int ch = ks * 2 + (lane >> 4);
                ldsm_x4(afr[mt], sb + aOff[s] + row * 128 + ((ch ^ (row & 7)) << 4));
            }
#pragma unroll
            for (int nt = 0; nt < 4; nt++) {
                int row = wn * 32 + nt * 8 + (il & 7);
                int ch = ks * 2 + (il >> 3);
                ldsm_x2(bfr[nt], sb + bOff[s] + row * 128 + ((ch ^ (row & 7)) << 4));
            }
#pragma unroll
            for (int mt = 0; mt < 4; mt++)
#pragma unroll
                for (int nt = 0; nt < 4; nt++)
                    mma_bf16(acc[mt * 4 + nt], afr[mt], bfr[nt]);
        }
        __syncthreads();
    }

    // epilogue: += lt[prev_label(row)], write g_gx
    int r_in = lane >> 2, c2 = (lane & 3) * 2;
#pragma unroll
    for (int mt = 0; mt < 4; mt++) {
        int r0 = m0 + wm * 64 + mt * 16 + r_in;
        int r1 = r0 + 8;
        int t0 = r0 >> 6, bb0 = r0 & 63;
        int t1 = r1 >> 6, bb1 = r1 & 63;
        int p0 = (t0 == 0) ? 0 : clamp_lab(lab[bb0 * Sn + t0 - 1]);
        int p1 = (t1 == 0) ? 0 : clamp_lab(lab[bb1 * Sn + t1 - 1]);
        const float* lt0 = g_lt + (size_t)p0 * G3;
        const float* lt1 = g_lt + (size_t)p1 * G3;
        float* o0 = g_gx + (size_t)r0 * G3;
        float* o1 = g_gx + (size_t)r1 * G3;
#pragma unroll
        for (int nt = 0; nt < 4; nt++) {
            int n = n0 + wn * 32 + nt * 8 + c2;
            float* a = acc[mt * 4 + nt];
            float2 v0, v1;
            v0.x = a[0] + lt0[n]; v0.y = a[1] + lt0[n + 1];
            v1.x = a[2] + lt1[n]; v1.y = a[3] + lt1[n + 1];
            *(float2*)(o0 + n) = v0;
            *(float2*)(o1 + n) = v1;
        }
    }
}

// ---------------- k_scan: persistent GRU scan (FFMA2 inner loop) ----------
__global__ void __launch_bounds__(TPB, 1) k_scan(const float* __restrict__ w_hh,
                                                 const float* __restrict__ b_hh) {
    extern __shared__ float sm[];
    float* w_sm  = sm;                       // [24][1024]
    float* h_sm  = sm + 24 * 1024;           // [64][132]
    float* gh_sm = h_sm + 64 * 132;          // [64][24]
    __shared__ float bhh_s[24];

    int cta = blockIdx.x;
    int tid = threadIdx.x;
    int c0  = cta * 8;

    for (int idx = tid; idx < 24 * 1024; idx += TPB) {
        int j = idx >> 10, k = idx & 1023;
        int wrow = (j >> 3) * Hn + c0 + (j & 7);
        w_sm[idx] = w_hh[(size_t)wrow * Hn + k];
    }
    if (tid < 24) bhh_s[tid] = b_hh[(tid >> 3) * Hn + c0 + (tid & 7)];

    for (int idx = cta * TPB + tid; idx < Bn * Hn; idx += NCTA * TPB)
        g_h[0][idx] = 0.f;
    gbar();

    int i0 = tid & 31, i1 = i0 + 32;
    int j0 = (tid >> 5) * 3;

    for (int t = 0; t < Sn; t++) {
        const float* hp  = g_h[t & 1];
        float*       hnx = g_h[(t + 1) & 1];
        unsigned long long acc2[6] = {0ull, 0ull, 0ull, 0ull, 0ull, 0ull};

        for (int kc = 0; kc < 8; kc++) {
#pragma unroll
            for (int q = 0; q < 8; q++) {
                int lin = tid + q * TPB;
                int r = lin >> 5, kk = (lin & 31) << 2;
                float4 v = *(const float4*)(hp + (size_t)r * Hn + kc * 128 + kk);
                *(float4*)(h_sm + r * 132 + kk) = v;
            }
            __syncthreads();
            const float* wbase = w_sm + kc * 128;
#pragma unroll 8
            for (int kq = 0; kq < 32; kq++) {
                int kk = kq << 2;
                ulonglong2 ha = *(const ulonglong2*)(h_sm + i0 * 132 + kk);
                ulonglong2 hb = *(const ulonglong2*)(h_sm + i1 * 132 + kk);
                ulonglong2 w0 = *(const ulonglong2*)(wbase + (j0 + 0) * 1024 + kk);
                ulonglong2 w1 = *(const ulonglong2*)(wbase + (j0 + 1) * 1024 + kk);
                ulonglong2 w2 = *(const ulonglong2*)(wbase + (j0 + 2) * 1024 + kk);
                acc2[0] = ffma2(ha.x, w0.x, acc2[0]); acc2[0] = ffma2(ha.y, w0.y, acc2[0]);
                acc2[1] = ffma2(ha.x, w1.x, acc2[1]); acc2[1] = ffma2(ha.y, w1.y, acc2[1]);
                acc2[2] = ffma2(ha.x, w2.x, acc2[2]); acc2[2] = ffma2(ha.y, w2.y, acc2[2]);
                acc2[3] = ffma2(hb.x, w0.x, acc2[3]); acc2[3] = ffma2(hb.y, w0.y, acc2[3]);
                acc2[4] = ffma2(hb.x, w1.x, acc2[4]); acc2[4] = ffma2(hb.y, w1.y, acc2[4]);
                acc2[5] = ffma2(hb.x, w2.x, acc2[5]); acc2[5] = ffma2(hb.y, w2.y, acc2[5]);
            }
            __syncthreads();
        }

        gh_sm[i0 * 24 + j0 + 0] = f2sum(acc2[0]);
        gh_sm[i0 * 24 + j0 + 1] = f2sum(acc2[1]);
        gh_sm[i0 * 24 + j0 + 2] = f2sum(acc2[2]);
        gh_sm[i1 * 24 + j0 + 0] = f2sum(acc2[3]);
        gh_sm[i1 * 24 + j0 + 1] = f2sum(acc2[4]);
        gh_sm[i1 * 24 + j0 + 2] = f2sum(acc2[5]);
        __syncthreads();

        const float* gxt = g_gx + (size_t)t * (Bn * G3);
#pragma unroll
        for (int q = 0; q < 2; q++) {
            int task = tid + q * TPB;
            int i = task >> 3, c = task & 7;
            int gc = c0 + c;
            float ghr = gh_sm[i * 24 + c]      + bhh_s[c];
            float ghz = gh_sm[i * 24 + 8 + c]  + bhh_s[8 + c];
            float ghn = gh_sm[i * 24 + 16 + c] + bhh_s[16 + c];
            const float* gxr = gxt + (size_t)i * G3 + gc;
            float r = 1.f / (1.f + expf(-(gxr[0]    + ghr)));
            float z = 1.f / (1.f + expf(-(gxr[1024] + ghz)));
            float n = tanhf(gxr[2048] + r * ghn);
            float hprev = hp[i * Hn + gc];
            float hnew = (1.f - z) * n + z * hprev;
            hnx[i * Hn + gc] = hnew;
            g_outs[(size_t)i * (Sn * Hn) + (size_t)t * Hn + gc] = hnew;
        }
        gbar();
    }
}

// ---------------- k_logits ----------------
__global__ void __launch_bounds__(256) k_logits(const int* __restrict__ lab,
                                                const float* __restrict__ w_out,
                                                const float* __restrict__ b_out,
                                                float* __restrict__ out) {
    __shared__ float a_sm[16][68];
    __shared__ float b_sm[16][64];
    int m0 = blockIdx.x * 64;
    int tid = threadIdx.x;

    int ar = tid >> 2, akq = tid & 3;
    int bl = tid & 63, bkq = tid >> 6;
    const float* aptr = g_outs + (size_t)(m0 + ar) * Hn + akq * 4;
    int ty = tid >> 4, tx = tid & 15;

    float acc[4][4];
#pragma unroll
    for (int q = 0; q < 4; q++)
#pragma unroll
        for (int p = 0; p < 4; p++) acc[q][p] = 0.f;

    float4 av = *(const float4*)(aptr);
    float4 bv = make_float4(0.f, 0.f, 0.f, 0.f);
    if (bl < Ln) bv = *(const float4*)(w_out + (size_t)bl * Hn + bkq * 4);

    for (int k0 = 0; k0 < Hn; k0 += 16) {
        a_sm[akq * 4 + 0][ar] = av.x;
        a_sm[akq * 4 + 1][ar] = av.y;
        a_sm[akq * 4 + 2][ar] = av.z;
        a_sm[akq * 4 + 3][ar] = av.w;
        b_sm[bkq * 4 + 0][bl] = bv.x;
        b_sm[bkq * 4 + 1][bl] = bv.y;
        b_sm[bkq * 4 + 2][bl] = bv.z;
        b_sm[bkq * 4 + 3][bl] = bv.w;
        __syncthreads();
        if (k0 + 16 < Hn) {
            av = *(const float4*)(aptr + k0 + 16);
            if (bl < Ln) bv = *(const float4*)(w_out + (size_t)bl * Hn + bkq * 4 + k0 + 16);
        }
#pragma unroll
        for (int kk = 0; kk < 16; kk++) {
            float4 a4 = *(const float4*)&a_sm[kk][ty * 4];
            float4 b4 = *(const float4*)&b_sm[kk][tx * 4];
#pragma unroll
            for (int q = 0; q < 4; q++) {
                float aval = (q == 0) ? a4.x : (q == 1) ? a4.y : (q == 2) ? a4.z : a4.w;
                acc[q][0] = fmaf(aval, b4.x, acc[q][0]);
                acc[q][1] = fmaf(aval, b4.y, acc[q][1]);
                acc[q][2] = fmaf(aval, b4.z, acc[q][2]);
                acc[q][3] = fmaf(aval, b4.w, acc[q][3]);
            }
        }
        __syncthreads();
    }

#pragma unroll
    for (int q = 0; q < 4; q++) {
        int row = m0 + ty * 4 + q;
        int b = row >> 9, t = row & 511;
        int prev = (t == 0) ? 0 : clamp_lab(lab[b * Sn + t - 1]);
#pragma unroll
        for (int p = 0; p < 4; p++) {
            int l = tx * 4 + p;
            if (l < Ln) {
                float v = allowf(prev, l) ? (acc[q][p] + b_out[l]) : NEGV;
                out[(size_t)row * Ln + l] = v;
            }
        }
    }
}

// ---------------- launcher ----------------
extern "C" void kernel_launch(void* const* d_in, const int* in_sizes, int n_in,
                              void* d_out, int out_size) {
    const float* we    = nullptr;
    const int*   lab   = nullptr;
    const float* emb   = nullptr;
    const float* w_ih  = nullptr;
    const float* w_hh  = nullptr;
    const float* b_ih  = nullptr;
    const float* b_hh  = nullptr;
    const float* w_out = nullptr;
    const float* b_out = nullptr;

    for (int i = 0; i < n_in; i++) {
        int n = in_sizes[i];
        const void* p = d_in[i];
        switch (n) {
            case 33554432: we    = (const float*)p; break;
            case 32768:    lab   = (const int*)p;   break;
            case 6272:     emb   = (const float*)p; break;
            case 3538944:  w_ih  = (const float*)p; break;
            case 3145728:  w_hh  = (const float*)p; break;
            case 50176:    w_out = (const float*)p; break;
            case 49:       b_out = (const float*)p; break;
            case 3072:
                if (!b_ih) b_ih = (const float*)p; else b_hh = (const float*)p;
                break;
            default: break;
        }
    }
    float* out = (float*)d_out;

    cudaFuncSetAttribute(k_scan,   cudaFuncAttributeMaxDynamicSharedMemorySize, SCAN_SMEM);
    cudaFuncSetAttribute(k_gx_mma, cudaFuncAttributeMaxDynamicSharedMemorySize, GX_SMEM);

    k_lt     <<<dim3(24, Ln), 128>>>(emb, w_ih, b_ih);
    k_cast_a <<<16384, 256>>>(we);
    k_cast_b <<<1536, 256>>>(w_ih);
    k_gx_mma <<<dim3(24, 256), 256, GX_SMEM>>>(lab);
    k_scan   <<<NCTA, TPB, SCAN_SMEM>>>(w_hh, b_hh);
    k_logits <<<Bn * Sn / 64, 256>>>(lab, w_out, b_out, out);
}

// round 5
// speedup vs baseline: 2.5910x; 1.9117x over previous
#include <cuda_runtime.h>
#include <cuda_bf16.h>
#include <math.h>

#define Bn 64
#define Sn 512
#define Hn 1024
#define En 128
#define Ln 49
#define G3 3072            // 3*H
#define IW 1152            // E+H
#define NEGV (-1e12f)

#define NCTA 128
#define TPB  256

// k_gx_mma: 128x128 CTA tile, K staged 64 wide, double buffered
#define GX_SMEM (2 * 2 * 128 * 64 * 2)   // 65536

// k_scan_tc smem: w 48KB + h 16KB + psum 12KB
#define SCANTC_SMEM (49152 + 16384 + 12288)

// ---------------- device scratch ----------------
__device__ __align__(16) float g_gx[(size_t)Bn * Sn * G3];     // [t][b][3H]
__device__ __align__(16) float g_outs[(size_t)Bn * Sn * Hn];   // [b][t][H]
__device__ __align__(16) float g_lt[Ln * G3];
__device__ __align__(16) float g_h[2][Bn * Hn];                // fp32 ping-pong
__device__ __align__(16) __nv_bfloat16 g_hbf[2][Bn * Hn];      // bf16 mirror ping-pong
__device__ __align__(16) uint4 g_abf[(size_t)Bn * Sn * 128];   // bf16 A [m=t*64+b][1024]
__device__ __align__(16) uint4 g_bbf[(size_t)G3 * 128];        // bf16 B [g][1024]
__device__ unsigned g_bar_count;
__device__ unsigned g_bar_gen;

// ---------------- PTX helpers ----------------
__device__ __forceinline__ unsigned smem_u32(const void* p) {
    unsigned a;
    asm("{ .reg .u64 t; cvta.to.shared.u64 t, %1; cvt.u32.u64 %0, t; }" : "=r"(a) : "l"(p));
    return a;
}
__device__ __forceinline__ void ldsm_x4(unsigned* r, unsigned addr) {
    asm volatile("ldmatrix.sync.aligned.m8n8.x4.shared.b16 {%0,%1,%2,%3}, [%4];"
                 : "=r"(r[0]), "=r"(r[1]), "=r"(r[2]), "=r"(r[3]) : "r"(addr));
}
__device__ __forceinline__ void ldsm_x2(unsigned* r, unsigned addr) {
    asm volatile("ldmatrix.sync.aligned.m8n8.x2.shared.b16 {%0,%1}, [%2];"
                 : "=r"(r[0]), "=r"(r[1]) : "r"(addr));
}
__device__ __forceinline__ void mma_bf16(float* c, const unsigned* a, const unsigned* b) {
    asm volatile(
        "mma.sync.aligned.m16n8k16.row.col.f32.bf16.bf16.f32 "
        "{%0,%1,%2,%3}, {%4,%5,%6,%7}, {%8,%9}, {%0,%1,%2,%3};"
        : "+f"(c[0]), "+f"(c[1]), "+f"(c[2]), "+f"(c[3])
        : "r"(a[0]), "r"(a[1]), "r"(a[2]), "r"(a[3]), "r"(b[0]), "r"(b[1]));
}

// ---------------- grid barrier ----------------
__device__ __forceinline__ void gbar() {
    __threadfence();
    __syncthreads();
    if (threadIdx.x == 0) {
        unsigned gen = *((volatile unsigned*)&g_bar_gen);
        unsigned old = atomicAdd(&g_bar_count, 1u);
        if (old == NCTA - 1) {
            g_bar_count = 0;
            __threadfence();
            atomicExch(&g_bar_gen, gen + 1u);
        } else {
            while (*((volatile unsigned*)&g_bar_gen) == gen) {}
            __threadfence();
        }
    }
    __syncthreads();
}

// ---------------- IOBES ----------------
__device__ __forceinline__ bool allowf(int prev, int nxt) {
    if (prev == 0 || ((prev - 1) & 3) >= 2) {
        if (nxt == 0) return true;
        int np = (nxt - 1) & 3;
        return (np == 0) || (np == 3);
    } else {
        if (nxt == 0) return false;
        int np = (nxt - 1) & 3;
        return (((nxt - 1) >> 2) == ((prev - 1) >> 2)) && (np == 1 || np == 2);
    }
}
__device__ __forceinline__ int clamp_lab(int v) {
    return v < 0 ? 0 : (v > Ln - 1 ? Ln - 1 : v);
}

// ---------------- k_lt ----------------
__global__ void k_lt(const float* __restrict__ emb,
                     const float* __restrict__ w_ih,
                     const float* __restrict__ b_ih) {
    int l = blockIdx.y;
    int g = blockIdx.x * 128 + threadIdx.x;
    __shared__ float es[En];
    if (threadIdx.x < En) es[threadIdx.x] = emb[l * En + threadIdx.x];
    __syncthreads();
    float acc = b_ih[g];
    const float* w = w_ih + (size_t)g * IW;
#pragma unroll 8
    for (int e = 0; e < En; e++) acc = fmaf(es[e], w[e], acc);
    g_lt[l * G3 + g] = acc;
}

// ---------------- bf16 cast kernels ----------------
__device__ __forceinline__ unsigned pk2(float a, float b) {
    __nv_bfloat162 h = __floats2bfloat162_rn(a, b);
    return *(unsigned*)&h;
}
__global__ void k_cast_a(const float* __restrict__ we) {
    size_t c = (size_t)blockIdx.x * 256 + threadIdx.x;
    int m = (int)(c >> 7), kq = (int)(c & 127);
    int t = m >> 6, b = m & 63;
    const float4* src = (const float4*)(we + ((size_t)b * Sn + t) * Hn + kq * 8);
    float4 f0 = src[0], f1 = src[1];
    uint4 o;
    o.x = pk2(f0.x, f0.y); o.y = pk2(f0.z, f0.w);
    o.z = pk2(f1.x, f1.y); o.w = pk2(f1.z, f1.w);
    g_abf[c] = o;
}
__global__ void k_cast_b(const float* __restrict__ w_ih) {
    size_t c = (size_t)blockIdx.x * 256 + threadIdx.x;
    int g = (int)(c >> 7), kq = (int)(c & 127);
    const float4* src = (const float4*)(w_ih + (size_t)g * IW + En + kq * 8);
    float4 f0 = src[0], f1 = src[1];
    uint4 o;
    o.x = pk2(f0.x, f0.y); o.y = pk2(f0.z, f0.w);
    o.z = pk2(f1.x, f1.y); o.w = pk2(f1.z, f1.w);
    g_bbf[c] = o;
}

// ---------------- k_gx_mma: HMMA bf16 GEMM + lt epilogue ------------------
__global__ void __launch_bounds__(256, 1) k_gx_mma(const int* __restrict__ lab) {
    extern __shared__ char smem[];
    unsigned sb = smem_u32(smem);
    const unsigned aOff[2] = { 0u, 32768u };
    const unsigned bOff[2] = { 16384u, 49152u };

    int tid = threadIdx.x, lane = tid & 31, wid = tid >> 5;
    int wm = wid >> 2, wn = wid & 3;
    int n0 = blockIdx.x * 128;
    int m0 = blockIdx.y * 128;

    float acc[16][4];
#pragma unroll
    for (int i = 0; i < 16; i++)
#pragma unroll
        for (int j = 0; j < 4; j++) acc[i][j] = 0.f;

    uint4 ra[4], rb[4];
#pragma unroll
    for (int q = 0; q < 4; q++) {
        int idx = tid * 4 + q, r = idx >> 3, i = idx & 7;
        ra[q] = g_abf[(size_t)(m0 + r) * 128 + i];
        rb[q] = g_bbf[(size_t)(n0 + r) * 128 + i];
    }

    int il = lane & 15;
    for (int kc = 0; kc < 16; kc++) {
        int s = kc & 1;
#pragma unroll
        for (int q = 0; q < 4; q++) {
            int idx = tid * 4 + q, r = idx >> 3, i = idx & 7;
            unsigned off = (unsigned)(r * 128 + ((i ^ (r & 7)) << 4));
            *(uint4*)(smem + aOff[s] + off) = ra[q];
            *(uint4*)(smem + bOff[s] + off) = rb[q];
        }
        __syncthreads();
        if (kc + 1 < 16) {
#pragma unroll
            for (int q = 0; q < 4; q++) {
                int idx = tid * 4 + q, r = idx >> 3, i = idx & 7;
                ra[q] = g_abf[(size_t)(m0 + r) * 128 + (kc + 1) * 8 + i];
                rb[q] = g_bbf[(size_t)(n0 + r) * 128 + (kc + 1) * 8 + i];
            }
        }
#pragma unroll
        for (int ks = 0; ks < 4; ks++) {
            unsigned afr[4][4], bfr[4][2];
#pragma unroll
            for (int mt = 0; mt < 4; mt++) {
                int row = wm * 64 + mt * 16 + il;
                int ch = ks * 2 + (lane >> 4);
                ldsm_x4(afr[mt], sb + aOff[s] + row * 128 + ((ch ^ (row & 7)) << 4));
            }
#pragma unroll
            for (int nt = 0; nt < 4; nt++) {
                int row = wn * 32 + nt * 8 + (il & 7);
                int ch = ks * 2 + (il >> 3);
                ldsm_x2(bfr[nt], sb + bOff[s] + row * 128 + ((ch ^ (row & 7)) << 4));
            }
#pragma unroll
            for (int mt = 0; mt < 4; mt++)
#pragma unroll
                for (int nt = 0; nt < 4; nt++)
                    mma_bf16(acc[mt * 4 + nt], afr[mt], bfr[nt]);
        }
        __syncthreads();
    }

    int r_in = lane >> 2, c2 = (lane & 3) * 2;
#pragma unroll
    for (int mt = 0; mt < 4; mt++) {
        int r0 = m0 + wm * 64 + mt * 16 + r_in;
        int r1 = r0 + 8;
        int t0 = r0 >> 6, bb0 = r0 & 63;
        int t1 = r1 >> 6, bb1 = r1 & 63;
        int p0 = (t0 == 0) ? 0 : clamp_lab(lab[bb0 * Sn + t0 - 1]);
        int p1 = (t1 == 0) ? 0 : clamp_lab(lab[bb1 * Sn + t1 - 1]);
        const float* lt0 = g_lt + (size_t)p0 * G3;
        const float* lt1 = g_lt + (size_t)p1 * G3;
        float* o0 = g_gx + (size_t)r0 * G3;
        float* o1 = g_gx + (size_t)r1 * G3;
#pragma unroll
        for (int nt = 0; nt < 4; nt++) {
            int n = n0 + wn * 32 + nt * 8 + c2;
            float* a = acc[mt * 4 + nt];
            float2 v0, v1;
            v0.x = a[0] + lt0[n]; v0.y = a[1] + lt0[n + 1];
            v1.x = a[2] + lt1[n]; v1.y = a[3] + lt1[n + 1];
            *(float2*)(o0 + n) = v0;
            *(float2*)(o1 + n) = v1;
        }
    }
}

// ---------------- k_scan_tc: persistent GRU scan on tensor cores ----------
// CTA owns 24 W rows (3 gates x 8 h-cols at c0=cta*8).
// Per step: gh[64x24] = h_bf16[64x1024] @ Wslice^T via m16n8k16 HMMA.
// 8 warps = 4 m-tiles (16 rows) x 2 k-halves; psum reduce; fp32 epilogue.
__global__ void __launch_bounds__(TPB, 1) k_scan_tc(const float* __restrict__ w_hh,
                                                    const float* __restrict__ b_hh) {
    extern __shared__ char smem[];
    unsigned sb = smem_u32(smem);
    char* w_sm = smem;                 // bf16 [8 kc][24 j][128], swizzled 16B chunks
    char* h_sm = smem + 49152;         // bf16 [64 r][128], swizzled
    float* psum = (float*)(smem + 65536);  // [2 kh][64][24]
    __shared__ float bhh_s[24];
    const unsigned sw = sb;            // w base
    const unsigned sh = sb + 49152;    // h base

    int cta = blockIdx.x, tid = threadIdx.x;
    int lane = tid & 31, wid = tid >> 5;
    int c0 = cta * 8;

    // ---- one-time: weights -> bf16 smem (ldmatrix layout) ----
    for (int cid = tid; cid < 3072; cid += TPB) {
        int j = cid >> 7, kchunk = cid & 127;          // j in 0..23, kchunk 16B units
        int kc = kchunk >> 4, c16 = kchunk & 15;
        int wrow = (j >> 3) * Hn + c0 + (j & 7);
        const float4* s = (const float4*)(w_hh + (size_t)wrow * Hn + kchunk * 8);
        float4 f0 = s[0], f1 = s[1];
        uint4 o;
        o.x = pk2(f0.x, f0.y); o.y = pk2(f0.z, f0.w);
        o.z = pk2(f1.x, f1.y); o.w = pk2(f1.z, f1.w);
        *(uint4*)(w_sm + kc * 6144 + j * 256 + ((c16 ^ (j & 7)) << 4)) = o;
    }
    if (tid < 24) bhh_s[tid] = b_hh[(tid >> 3) * Hn + c0 + (tid & 7)];

    // zero h buffers (fp32 + bf16)
    for (int idx = cta * TPB + tid; idx < Bn * Hn; idx += NCTA * TPB)
        g_h[0][idx] = 0.f;
    for (int idx = cta * TPB + tid; idx < Bn * Hn * 2 / 16; idx += NCTA * TPB)
        ((uint4*)g_hbf[0])[idx] = make_uint4(0u, 0u, 0u, 0u);
    gbar();

    int wm = wid & 3, kh = wid >> 2;
    int il = lane & 15;
    int r_in = lane >> 2, cc2 = (lane & 3) * 2;

    for (int t = 0; t < Sn; t++) {
        const __nv_bfloat16* hb = g_hbf[t & 1];
        float acc[3][4];
#pragma unroll
        for (int nt = 0; nt < 3; nt++)
#pragma unroll
            for (int j = 0; j < 4; j++) acc[nt][j] = 0.f;

        // prefetch chunk 0: [64 rows][128 bf16] = 1024 x 16B
        uint4 pre[4];
#pragma unroll
        for (int q = 0; q < 4; q++) {
            int idx = tid * 4 + q;
            int r = idx >> 4, c16 = idx & 15;
            pre[q] = *(const uint4*)(hb + (size_t)r * Hn + c16 * 8);
        }

        for (int kc = 0; kc < 8; kc++) {
#pragma unroll
            for (int q = 0; q < 4; q++) {
                int idx = tid * 4 + q;
                int r = idx >> 4, c16 = idx & 15;
                *(uint4*)(h_sm + r * 256 + ((c16 ^ (r & 7)) << 4)) = pre[q];
            }
            __syncthreads();
            if (kc + 1 < 8) {
#pragma unroll
                for (int q = 0; q < 4; q++) {
                    int idx = tid * 4 + q;
                    int r = idx >> 4, c16 = idx & 15;
                    pre[q] = *(const uint4*)(hb + (size_t)r * Hn + (kc + 1) * 128 + c16 * 8);
                }
            }
#pragma unroll
            for (int ks = 0; ks < 4; ks++) {
                int kk = kh * 4 + ks;                    // k16 index 0..7 in chunk
                unsigned a[4];
                {
                    int row = wm * 16 + il;
                    int ch = kk * 2 + (lane >> 4);
                    ldsm_x4(a, sh + row * 256 + ((ch ^ (row & 7)) << 4));
                }
                unsigned bfr[3][2];
#pragma unroll
                for (int nt = 0; nt < 3; nt++) {
                    int row = nt * 8 + (il & 7);
                    int ch = kk * 2 + (il >> 3);
                    ldsm_x2(bfr[nt], sw + kc * 6144 + row * 256 + ((ch ^ (row & 7)) << 4));
                }
#pragma unroll
                for (int nt = 0; nt < 3; nt++)
                    mma_bf16(acc[nt], a, bfr[nt]);
            }
            __syncthreads();
        }

        // write k-split partials
        float* ps = psum + kh * (64 * 24);
#pragma unroll
        for (int nt = 0; nt < 3; nt++) {
            int mr = wm * 16 + r_in;
            int n = nt * 8 + cc2;
            ps[mr * 24 + n]           = acc[nt][0];
            ps[mr * 24 + n + 1]       = acc[nt][1];
            ps[(mr + 8) * 24 + n]     = acc[nt][2];
            ps[(mr + 8) * 24 + n + 1] = acc[nt][3];
        }
        __syncthreads();

        // epilogue: 64 batches x 8 cols
        const float* gxt = g_gx + (size_t)t * (Bn * G3);
        const float* hp  = g_h[t & 1];
        float*       hnx = g_h[(t + 1) & 1];
        __nv_bfloat16* hbn = g_hbf[(t + 1) & 1];
#pragma unroll
        for (int q = 0; q < 2; q++) {
            int task = tid + q * TPB;
            int i = task >> 3, c = task & 7;
            int gc = c0 + c;
            float ghr = psum[i * 24 + c]      + psum[64 * 24 + i * 24 + c]      + bhh_s[c];
            float ghz = psum[i * 24 + 8 + c]  + psum[64 * 24 + i * 24 + 8 + c]  + bhh_s[8 + c];
            float ghn = psum[i * 24 + 16 + c] + psum[64 * 24 + i * 24 + 16 + c] + bhh_s[16 + c];
            const float* gxr = gxt + (size_t)i * G3 + gc;
            float r = 1.f / (1.f + expf(-(gxr[0]    + ghr)));
            float z = 1.f / (1.f + expf(-(gxr[1024] + ghz)));
            float n = tanhf(gxr[2048] + r * ghn);
            float hprev = hp[i * Hn + gc];
            float hnew = (1.f - z) * n + z * hprev;
            hnx[i * Hn + gc] = hnew;
            g_outs[(size_t)i * (Sn * Hn) + (size_t)t * Hn + gc] = hnew;
            hbn[i * Hn + gc] = __float2bfloat16(hnew);
        }
        gbar();
    }
}

// ---------------- k_logits ----------------
__global__ void __launch_bounds__(256) k_logits(const int* __restrict__ lab,
                                                const float* __restrict__ w_out,
                                                const float* __restrict__ b_out,
                                                float* __restrict__ out) {
    __shared__ float a_sm[16][68];
    __shared__ float b_sm[16][64];
    int m0 = blockIdx.x * 64;
    int tid = threadIdx.x;

    int ar = tid >> 2, akq = tid & 3;
    int bl = tid & 63, bkq = tid >> 6;
    const float* aptr = g_outs + (size_t)(m0 + ar) * Hn + akq * 4;
    int ty = tid >> 4, tx = tid & 15;

    float acc[4][4];
#pragma unroll
    for (int q = 0; q < 4; q++)
#pragma unroll
        for (int p = 0; p < 4; p++) acc[q][p] = 0.f;

    float4 av = *(const float4*)(aptr);
    float4 bv = make_float4(0.f, 0.f, 0.f, 0.f);
    if (bl < Ln) bv = *(const float4*)(w_out + (size_t)bl * Hn + bkq * 4);

    for (int k0 = 0; k0 < Hn; k0 += 16) {
        a_sm[akq * 4 + 0][ar] = av.x;
        a_sm[akq * 4 + 1][ar] = av.y;
        a_sm[akq * 4 + 2][ar] = av.z;
        a_sm[akq * 4 + 3][ar] = av.w;
        b_sm[bkq * 4 + 0][bl] = bv.x;
        b_sm[bkq * 4 + 1][bl] = bv.y;
        b_sm[bkq * 4 + 2][bl] = bv.z;
        b_sm[bkq * 4 + 3][bl] = bv.w;
        __syncthreads();
        if (k0 + 16 < Hn) {
            av = *(const float4*)(aptr + k0 + 16);
            if (bl < Ln) bv = *(const float4*)(w_out + (size_t)bl * Hn + bkq * 4 + k0 + 16);
        }
#pragma unroll
        for (int kk = 0; kk < 16; kk++) {
            float4 a4 = *(const float4*)&a_sm[kk][ty * 4];
            float4 b4 = *(const float4*)&b_sm[kk][tx * 4];
#pragma unroll
            for (int q = 0; q < 4; q++) {
                float aval = (q == 0) ? a4.x : (q == 1) ? a4.y : (q == 2) ? a4.z : a4.w;
                acc[q][0] = fmaf(aval, b4.x, acc[q][0]);
                acc[q][1] = fmaf(aval, b4.y, acc[q][1]);
                acc[q][2] = fmaf(aval, b4.z, acc[q][2]);
                acc[q][3] = fmaf(aval, b4.w, acc[q][3]);
            }
        }
        __syncthreads();
    }

#pragma unroll
    for (int q = 0; q < 4; q++) {
        int row = m0 + ty * 4 + q;
        int b = row >> 9, t = row & 511;
        int prev = (t == 0) ? 0 : clamp_lab(lab[b * Sn + t - 1]);
#pragma unroll
        for (int p = 0; p < 4; p++) {
            int l = tx * 4 + p;
            if (l < Ln) {
                float v = allowf(prev, l) ? (acc[q][p] + b_out[l]) : NEGV;
                out[(size_t)row * Ln + l] = v;
            }
        }
    }
}

// ---------------- launcher ----------------
extern "C" void kernel_launch(void* const* d_in, const int* in_sizes, int n_in,
                              void* d_out, int out_size) {
    const float* we    = nullptr;
    const int*   lab   = nullptr;
    const float* emb   = nullptr;
    const float* w_ih  = nullptr;
    const float* w_hh  = nullptr;
    const float* b_ih  = nullptr;
    const float* b_hh  = nullptr;
    const float* w_out = nullptr;
    const float* b_out = nullptr;

    for (int i = 0; i < n_in; i++) {
        int n = in_sizes[i];
        const void* p = d_in[i];
        switch (n) {
            case 33554432: we    = (const float*)p; break;
            case 32768:    lab   = (const int*)p;   break;
            case 6272:     emb   = (const float*)p; break;
            case 3538944:  w_ih  = (const float*)p; break;
            case 3145728:  w_hh  = (const float*)p; break;
            case 50176:    w_out = (const float*)p; break;
            case 49:       b_out = (const float*)p; break;
            case 3072:
                if (!b_ih) b_ih = (const float*)p; else b_hh = (const float*)p;
                break;
            default: break;
        }
    }
    float* out = (float*)d_out;

    cudaFuncSetAttribute(k_gx_mma,  cudaFuncAttributeMaxDynamicSharedMemorySize, GX_SMEM);
    cudaFuncSetAttribute(k_scan_tc, cudaFuncAttributeMaxDynamicSharedMemorySize, SCANTC_SMEM);

    k_lt      <<<dim3(24, Ln), 128>>>(emb, w_ih, b_ih);
    k_cast_a  <<<16384, 256>>>(we);
    k_cast_b  <<<1536, 256>>>(w_ih);
    k_gx_mma  <<<dim3(24, 256), 256, GX_SMEM>>>(lab);
    k_scan_tc <<<NCTA, TPB, SCANTC_SMEM>>>(w_hh, b_hh);
    k_logits  <<<Bn * Sn / 64, 256>>>(lab, w_out, b_out, out);
}

// round 6
// speedup vs baseline: 3.2615x; 1.2588x over previous
#include <cuda_runtime.h>
#include <cuda_bf16.h>
#include <math.h>

#define Bn 64
#define Sn 512
#define Hn 1024
#define En 128
#define Ln 49
#define G3 3072            // 3*H
#define IW 1152            // E+H
#define NEGV (-1e12f)

#define NCTA 128
#define TPB  256

// k_gx_mma: 128x128 CTA tile, K staged 64 wide, double buffered
#define GX_SMEM (2 * 2 * 128 * 64 * 2)   // 65536

// k_scan_tc smem: w 48KB + h ping-pong 2x16KB + psum 12KB
#define SCANTC_SMEM (49152 + 32768 + 12288)

// ---------------- device scratch ----------------
__device__ __align__(16) float g_gx[(size_t)Bn * Sn * G3];     // [t][b][3H]
__device__ __align__(16) float g_outs[(size_t)Bn * Sn * Hn];   // [b][t][H]
__device__ __align__(16) float g_lt[Ln * G3];
__device__ __align__(16) __nv_bfloat16 g_hbf[2][Bn * Hn];      // bf16 h ping-pong
__device__ __align__(16) uint4 g_abf[(size_t)Bn * Sn * 128];   // bf16 A [m=t*64+b][1024]
__device__ __align__(16) uint4 g_bbf[(size_t)G3 * 128];        // bf16 B [g][1024]
__device__ unsigned g_grp[8];
__device__ unsigned g_root;
__device__ unsigned g_gen2;

// ---------------- PTX helpers ----------------
__device__ __forceinline__ unsigned smem_u32(const void* p) {
    unsigned a;
    asm("{ .reg .u64 t; cvta.to.shared.u64 t, %1; cvt.u32.u64 %0, t; }" : "=r"(a) : "l"(p));
    return a;
}
__device__ __forceinline__ void ldsm_x4(unsigned* r, unsigned addr) {
    asm volatile("ldmatrix.sync.aligned.m8n8.x4.shared.b16 {%0,%1,%2,%3}, [%4];"
                 : "=r"(r[0]), "=r"(r[1]), "=r"(r[2]), "=r"(r[3]) : "r"(addr));
}
__device__ __forceinline__ void ldsm_x2(unsigned* r, unsigned addr) {
    asm volatile("ldmatrix.sync.aligned.m8n8.x2.shared.b16 {%0,%1}, [%2];"
                 : "=r"(r[0]), "=r"(r[1]) : "r"(addr));
}
__device__ __forceinline__ void mma_bf16(float* c, const unsigned* a, const unsigned* b) {
    asm volatile(
        "mma.sync.aligned.m16n8k16.row.col.f32.bf16.bf16.f32 "
        "{%0,%1,%2,%3}, {%4,%5,%6,%7}, {%8,%9}, {%0,%1,%2,%3};"
        : "+f"(c[0]), "+f"(c[1]), "+f"(c[2]), "+f"(c[3])
        : "r"(a[0]), "r"(a[1]), "r"(a[2]), "r"(a[3]), "r"(b[0]), "r"(b[1]));
}
__device__ __forceinline__ float tanhfast(float x) {
    float y;
    asm("tanh.approx.f32 %0, %1;" : "=f"(y) : "f"(x));
    return y;
}
__device__ __forceinline__ float sigfast(float x) {
    return __fdividef(1.f, 1.f + __expf(-x));
}

// ---------------- two-level grid barrier ----------------
__device__ __forceinline__ void gbar2(int cta) {
    __threadfence();
    __syncthreads();
    if (threadIdx.x == 0) {
        unsigned gen = *((volatile unsigned*)&g_gen2);
        int grp = cta >> 4;
        if (atomicAdd(&g_grp[grp], 1u) == 15u) {
            atomicExch(&g_grp[grp], 0u);
            if (atomicAdd(&g_root, 1u) == 7u) {
                atomicExch(&g_root, 0u);
                __threadfence();
                atomicExch(&g_gen2, gen + 1u);
            }
        }
        while (*((volatile unsigned*)&g_gen2) == gen) {}
        __threadfence();
    }
    __syncthreads();
}

// ---------------- IOBES ----------------
__device__ __forceinline__ bool allowf(int prev, int nxt) {
    if (prev == 0 || ((prev - 1) & 3) >= 2) {
        if (nxt == 0) return true;
        int np = (nxt - 1) & 3;
        return (np == 0) || (np == 3);
    } else {
        if (nxt == 0) return false;
        int np = (nxt - 1) & 3;
        return (((nxt - 1) >> 2) == ((prev - 1) >> 2)) && (np == 1 || np == 2);
    }
}
__device__ __forceinline__ int clamp_lab(int v) {
    return v < 0 ? 0 : (v > Ln - 1 ? Ln - 1 : v);
}

// ---------------- k_lt ----------------
__global__ void k_lt(const float* __restrict__ emb,
                     const float* __restrict__ w_ih,
                     const float* __restrict__ b_ih) {
    int l = blockIdx.y;
    int g = blockIdx.x * 128 + threadIdx.x;
    __shared__ float es[En];
    if (threadIdx.x < En) es[threadIdx.x] = emb[l * En + threadIdx.x];
    __syncthreads();
    float acc = b_ih[g];
    const float* w = w_ih + (size_t)g * IW;
#pragma unroll 8
    for (int e = 0; e < En; e++) acc = fmaf(es[e], w[e], acc);
    g_lt[l * G3 + g] = acc;
}

// ---------------- bf16 cast kernels ----------------
__device__ __forceinline__ unsigned pk2(float a, float b) {
    __nv_bfloat162 h = __floats2bfloat162_rn(a, b);
    return *(unsigned*)&h;
}
__global__ void k_cast_a(const float* __restrict__ we) {
    size_t c = (size_t)blockIdx.x * 256 + threadIdx.x;
    int m = (int)(c >> 7), kq = (int)(c & 127);
    int t = m >> 6, b = m & 63;
    const float4* src = (const float4*)(we + ((size_t)b * Sn + t) * Hn + kq * 8);
    float4 f0 = src[0], f1 = src[1];
    uint4 o;
    o.x = pk2(f0.x, f0.y); o.y = pk2(f0.z, f0.w);
    o.z = pk2(f1.x, f1.y); o.w = pk2(f1.z, f1.w);
    g_abf[c] = o;
}
__global__ void k_cast_b(const float* __restrict__ w_ih) {
    size_t c = (size_t)blockIdx.x * 256 + threadIdx.x;
    int g = (int)(c >> 7), kq = (int)(c & 127);
    const float4* src = (const float4*)(w_ih + (size_t)g * IW + En + kq * 8);
    float4 f0 = src[0], f1 = src[1];
    uint4 o;
    o.x = pk2(f0.x, f0.y); o.y = pk2(f0.z, f0.w);
    o.z = pk2(f1.x, f1.y); o.w = pk2(f1.z, f1.w);
    g_bbf[c] = o;
}

// ---------------- k_gx_mma: HMMA bf16 GEMM + lt epilogue ------------------
__global__ void __launch_bounds__(256, 1) k_gx_mma(const int* __restrict__ lab) {
    extern __shared__ char smem[];
    unsigned sb = smem_u32(smem);
    const unsigned aOff[2] = { 0u, 32768u };
    const unsigned bOff[2] = { 16384u, 49152u };

    int tid = threadIdx.x, lane = tid & 31, wid = tid >> 5;
    int wm = wid >> 2, wn = wid & 3;
    int n0 = blockIdx.x * 128;
    int m0 = blockIdx.y * 128;

    float acc[16][4];
#pragma unroll
    for (int i = 0; i < 16; i++)
#pragma unroll
        for (int j = 0; j < 4; j++) acc[i][j] = 0.f;

    uint4 ra[4], rb[4];
#pragma unroll
    for (int q = 0; q < 4; q++) {
        int idx = tid * 4 + q, r = idx >> 3, i = idx & 7;
        ra[q] = g_abf[(size_t)(m0 + r) * 128 + i];
        rb[q] = g_bbf[(size_t)(n0 + r) * 128 + i];
    }

    int il = lane & 15;
    for (int kc = 0; kc < 16; kc++) {
        int s = kc & 1;
#pragma unroll
        for (int q = 0; q < 4; q++) {
            int idx = tid * 4 + q, r = idx >> 3, i = idx & 7;
            unsigned off = (unsigned)(r * 128 + ((i ^ (r & 7)) << 4));
            *(uint4*)(smem + aOff[s] + off) = ra[q];
            *(uint4*)(smem + bOff[s] + off) = rb[q];
        }
        __syncthreads();
        if (kc + 1 < 16) {
#pragma unroll
            for (int q = 0; q < 4; q++) {
                int idx = tid * 4 + q, r = idx >> 3, i = idx & 7;
                ra[q] = g_abf[(size_t)(m0 + r) * 128 + (kc + 1) * 8 + i];
                rb[q] = g_bbf[(size_t)(n0 + r) * 128 + (kc + 1) * 8 + i];
            }
        }
#pragma unroll
        for (int ks = 0; ks < 4; ks++) {
            unsigned afr[4][4], bfr[4][2];
#pragma unroll
            for (int mt = 0; mt < 4; mt++) {
                int row = wm * 64 + mt * 16 + il;
                int ch = ks * 2 + (lane >> 4);
                ldsm_x4(afr[mt], sb + aOff[s] + row * 128 + ((ch ^ (row & 7)) << 4));
            }
#pragma unroll
            for (int nt = 0; nt < 4; nt++) {
                int row = wn * 32 + nt * 8 + (il & 7);
                int ch = ks * 2 + (il >> 3);
                ldsm_x2(bfr[nt], sb + bOff[s] + row * 128 + ((ch ^ (row & 7)) << 4));
            }
#pragma unroll
            for (int mt = 0; mt < 4; mt++)
#pragma unroll
                for (int nt = 0; nt < 4; nt++)
                    mma_bf16(acc[mt * 4 + nt], afr[mt], bfr[nt]);
        }
        __syncthreads();
    }

    int r_in = lane >> 2, c2 = (lane & 3) * 2;
#pragma unroll
    for (int mt = 0; mt < 4; mt++) {
        int r0 = m0 + wm * 64 + mt * 16 + r_in;
        int r1 = r0 + 8;
        int t0 = r0 >> 6, bb0 = r0 & 63;
        int t1 = r1 >> 6, bb1 = r1 & 63;
        int p0 = (t0 == 0) ? 0 : clamp_lab(lab[bb0 * Sn + t0 - 1]);
        int p1 = (t1 == 0) ? 0 : clamp_lab(lab[bb1 * Sn + t1 - 1]);
        const float* lt0 = g_lt + (size_t)p0 * G3;
        const float* lt1 = g_lt + (size_t)p1 * G3;
        float* o0 = g_gx + (size_t)r0 * G3;
        float* o1 = g_gx + (size_t)r1 * G3;
#pragma unroll
        for (int nt = 0; nt < 4; nt++) {
            int n = n0 + wn * 32 + nt * 8 + c2;
            float* a = acc[mt * 4 + nt];
            float2 v0, v1;
            v0.x = a[0] + lt0[n]; v0.y = a[1] + lt0[n + 1];
            v1.x = a[2] + lt1[n]; v1.y = a[3] + lt1[n + 1];
            *(float2*)(o0 + n) = v0;
            *(float2*)(o1 + n) = v1;
        }
    }
}

// ---------------- k_scan_tc: persistent GRU scan on tensor cores ----------
// CTA owns 24 W rows (3 gates x 8 h-cols at c0=cta*8).
// Per step: gh[64x24] = h_bf16[64x1024] @ Wslice^T via m16n8k16 HMMA.
// 8 warps = 4 m-tiles x 2 k-halves; h staged in ping-pong smem (1 sync/chunk);
// gx prefetched to regs; hprev carried in regs; two-level grid barrier.
__global__ void __launch_bounds__(TPB, 1) k_scan_tc(const float* __restrict__ w_hh,
                                                    const float* __restrict__ b_hh) {
    extern __shared__ char smem[];
    unsigned sb = smem_u32(smem);
    char* w_sm = smem;                      // bf16 [8 kc][24 j][128], swizzled
    char* h_sm = smem + 49152;              // 2 x bf16 [64 r][128], swizzled
    float* psum = (float*)(smem + 49152 + 32768);  // [2 kh][64][24]
    __shared__ float bhh_s[24];
    const unsigned sw = sb;
    const unsigned sh0 = sb + 49152;

    int cta = blockIdx.x, tid = threadIdx.x;
    int lane = tid & 31, wid = tid >> 5;
    int c0 = cta * 8;

    // one-time: weights -> bf16 smem (ldmatrix layout)
    for (int cid = tid; cid < 3072; cid += TPB) {
        int j = cid >> 7, kchunk = cid & 127;
        int kc = kchunk >> 4, c16 = kchunk & 15;
        int wrow = (j >> 3) * Hn + c0 + (j & 7);
        const float4* s = (const float4*)(w_hh + (size_t)wrow * Hn + kchunk * 8);
        float4 f0 = s[0], f1 = s[1];
        uint4 o;
        o.x = pk2(f0.x, f0.y); o.y = pk2(f0.z, f0.w);
        o.z = pk2(f1.x, f1.y); o.w = pk2(f1.z, f1.w);
        *(uint4*)(w_sm + kc * 6144 + j * 256 + ((c16 ^ (j & 7)) << 4)) = o;
    }
    if (tid < 24) bhh_s[tid] = b_hh[(tid >> 3) * Hn + c0 + (tid & 7)];

    // zero bf16 h buffer 0
    for (int idx = cta * TPB + tid; idx < Bn * Hn * 2 / 16; idx += NCTA * TPB)
        ((uint4*)g_hbf[0])[idx] = make_uint4(0u, 0u, 0u, 0u);
    gbar2(cta);

    int wm = wid & 3, kh = wid >> 2;
    int il = lane & 15;
    int r_in = lane >> 2, cc2 = (lane & 3) * 2;

    // epilogue task mapping (fixed per thread across steps)
    int ti[2], tc[2];
    ti[0] = tid >> 3;           tc[0] = tid & 7;
    ti[1] = (tid + TPB) >> 3;   tc[1] = tid & 7;
    float hprev[2] = { 0.f, 0.f };

    for (int t = 0; t < Sn; t++) {
        const __nv_bfloat16* hb = g_hbf[t & 1];
        const float* gxt = g_gx + (size_t)t * (Bn * G3);

        // prefetch epilogue gx values (DRAM, hidden under MMA phase)
        float gxa[2][3];
#pragma unroll
        for (int q = 0; q < 2; q++) {
            const float* gxr = gxt + (size_t)ti[q] * G3 + c0 + tc[q];
            gxa[q][0] = __ldg(gxr);
            gxa[q][1] = __ldg(gxr + 1024);
            gxa[q][2] = __ldg(gxr + 2048);
        }

        float acc[3][4];
#pragma unroll
        for (int nt = 0; nt < 3; nt++)
#pragma unroll
            for (int j = 0; j < 4; j++) acc[nt][j] = 0.f;

        // prefetch h chunk 0
        uint4 pre[4];
#pragma unroll
        for (int q = 0; q < 4; q++) {
            int idx = tid * 4 + q;
            int r = idx >> 4, c16 = idx & 15;
            pre[q] = *(const uint4*)(hb + (size_t)r * Hn + c16 * 8);
        }

        for (int kc = 0; kc < 8; kc++) {
            int s = kc & 1;
            char* hbuf = h_sm + s * 16384;
#pragma unroll
            for (int q = 0; q < 4; q++) {
                int idx = tid * 4 + q;
                int r = idx >> 4, c16 = idx & 15;
                *(uint4*)(hbuf + r * 256 + ((c16 ^ (r & 7)) << 4)) = pre[q];
            }
            if (kc + 1 < 8) {
#pragma unroll
                for (int q = 0; q < 4; q++) {
                    int idx = tid * 4 + q;
                    int r = idx >> 4, c16 = idx & 15;
                    pre[q] = *(const uint4*)(hb + (size_t)r * Hn + (kc + 1) * 128 + c16 * 8);
                }
            }
            __syncthreads();
            unsigned shb = sh0 + s * 16384;
#pragma unroll
            for (int ks = 0; ks < 4; ks++) {
                int kk = kh * 4 + ks;
                unsigned a[4];
                {
                    int row = wm * 16 + il;
                    int ch = kk * 2 + (lane >> 4);
                    ldsm_x4(a, shb + row * 256 + ((ch ^ (row & 7)) << 4));
                }
                unsigned bfr[3][2];
#pragma unroll
                for (int nt = 0; nt < 3; nt++) {
                    int row = nt * 8 + (il & 7);
                    int ch = kk * 2 + (il >> 3);
                    ldsm_x2(bfr[nt], sw + kc * 6144 + row * 256 + ((ch ^ (row & 7)) << 4));
                }
#pragma unroll
                for (int nt = 0; nt < 3; nt++)
                    mma_bf16(acc[nt], a, bfr[nt]);
            }
        }

        // write k-split partials
        float* ps = psum + kh * (64 * 24);
#pragma unroll
        for (int nt = 0; nt < 3; nt++) {
            int mr = wm * 16 + r_in;
            int n = nt * 8 + cc2;
            ps[mr * 24 + n]           = acc[nt][0];
            ps[mr * 24 + n + 1]       = acc[nt][1];
            ps[(mr + 8) * 24 + n]     = acc[nt][2];
            ps[(mr + 8) * 24 + n + 1] = acc[nt][3];
        }
        __syncthreads();

        // epilogue
        float* hnx_outs = g_outs;
        __nv_bfloat16* hbn = g_hbf[(t + 1) & 1];
#pragma unroll
        for (int q = 0; q < 2; q++) {
            int i = ti[q], c = tc[q];
            int gc = c0 + c;
            float ghr = psum[i * 24 + c]      + psum[64 * 24 + i * 24 + c]      + bhh_s[c];
            float ghz = psum[i * 24 + 8 + c]  + psum[64 * 24 + i * 24 + 8 + c]  + bhh_s[8 + c];
            float ghn = psum[i * 24 + 16 + c] + psum[64 * 24 + i * 24 + 16 + c] + bhh_s[16 + c];
            float r = sigfast(gxa[q][0] + ghr);
            float z = sigfast(gxa[q][1] + ghz);
            float n = tanhfast(gxa[q][2] + r * ghn);
            float hnew = (1.f - z) * n + z * hprev[q];
            hprev[q] = hnew;
            hnx_outs[(size_t)i * (Sn * Hn) + (size_t)t * Hn + gc] = hnew;
            hbn[i * Hn + gc] = __float2bfloat16(hnew);
        }
        gbar2(cta);
    }
}

// ---------------- k_logits ----------------
__global__ void __launch_bounds__(256) k_logits(const int* __restrict__ lab,
                                                const float* __restrict__ w_out,
                                                const float* __restrict__ b_out,
                                                float* __restrict__ out) {
    __shared__ float a_sm[16][68];
    __shared__ float b_sm[16][64];
    int m0 = blockIdx.x * 64;
    int tid = threadIdx.x;

    int ar = tid >> 2, akq = tid & 3;
    int bl = tid & 63, bkq = tid >> 6;
    const float* aptr = g_outs + (size_t)(m0 + ar) * Hn + akq * 4;
    int ty = tid >> 4, tx = tid & 15;

    float acc[4][4];
#pragma unroll
    for (int q = 0; q < 4; q++)
#pragma unroll
        for (int p = 0; p < 4; p++) acc[q][p] = 0.f;

    float4 av = *(const float4*)(aptr);
    float4 bv = make_float4(0.f, 0.f, 0.f, 0.f);
    if (bl < Ln) bv = *(const float4*)(w_out + (size_t)bl * Hn + bkq * 4);

    for (int k0 = 0; k0 < Hn; k0 += 16) {
        a_sm[akq * 4 + 0][ar] = av.x;
        a_sm[akq * 4 + 1][ar] = av.y;
        a_sm[akq * 4 + 2][ar] = av.z;
        a_sm[akq * 4 + 3][ar] = av.w;
        b_sm[bkq * 4 + 0][bl] = bv.x;
        b_sm[bkq * 4 + 1][bl] = bv.y;
        b_sm[bkq * 4 + 2][bl] = bv.z;
        b_sm[bkq * 4 + 3][bl] = bv.w;
        __syncthreads();
        if (k0 + 16 < Hn) {
            av = *(const float4*)(aptr + k0 + 16);
            if (bl < Ln) bv = *(const float4*)(w_out + (size_t)bl * Hn + bkq * 4 + k0 + 16);
        }
#pragma unroll
        for (int kk = 0; kk < 16; kk++) {
            float4 a4 = *(const float4*)&a_sm[kk][ty * 4];
            float4 b4 = *(const float4*)&b_sm[kk][tx * 4];
#pragma unroll
            for (int q = 0; q < 4; q++) {
                float aval = (q == 0) ? a4.x : (q == 1) ? a4.y : (q == 2) ? a4.z : a4.w;
                acc[q][0] = fmaf(aval, b4.x, acc[q][0]);
                acc[q][1] = fmaf(aval, b4.y, acc[q][1]);
                acc[q][2] = fmaf(aval, b4.z, acc[q][2]);
                acc[q][3] = fmaf(aval, b4.w, acc[q][3]);
            }
        }
        __syncthreads();
    }

#pragma unroll
    for (int q = 0; q < 4; q++) {
        int row = m0 + ty * 4 + q;
        int b = row >> 9, t = row & 511;
        int prev = (t == 0) ? 0 : clamp_lab(lab[b * Sn + t - 1]);
#pragma unroll
        for (int p = 0; p < 4; p++) {
            int l = tx * 4 + p;
            if (l < Ln) {
                float v = allowf(prev, l) ? (acc[q][p] + b_out[l]) : NEGV;
                out[(size_t)row * Ln + l] = v;
            }
        }
    }
}

// ---------------- launcher ----------------
extern "C" void kernel_launch(void* const* d_in, const int* in_sizes, int n_in,
                              void* d_out, int out_size) {
    const float* we    = nullptr;
    const int*   lab   = nullptr;
    const float* emb   = nullptr;
    const float* w_ih  = nullptr;
    const float* w_hh  = nullptr;
    const float* b_ih  = nullptr;
    const float* b_hh  = nullptr;
    const float* w_out = nullptr;
    const float* b_out = nullptr;

    for (int i = 0; i < n_in; i++) {
        int n = in_sizes[i];
        const void* p = d_in[i];
        switch (n) {
            case 33554432: we    = (const float*)p; break;
            case 32768:    lab   = (const int*)p;   break;
            case 6272:     emb   = (const float*)p; break;
            case 3538944:  w_ih  = (const float*)p; break;
            case 3145728:  w_hh  = (const float*)p; break;
            case 50176:    w_out = (const float*)p; break;
            case 49:       b_out = (const float*)p; break;
            case 3072:
                if (!b_ih) b_ih = (const float*)p; else b_hh = (const float*)p;
                break;
            default: break;
        }
    }
    float* out = (float*)d_out;

    cudaFuncSetAttribute(k_gx_mma,  cudaFuncAttributeMaxDynamicSharedMemorySize, GX_SMEM);
    cudaFuncSetAttribute(k_scan_tc, cudaFuncAttributeMaxDynamicSharedMemorySize, SCANTC_SMEM);

    k_lt      <<<dim3(24, Ln), 128>>>(emb, w_ih, b_ih);
    k_cast_a  <<<16384, 256>>>(we);
    k_cast_b  <<<1536, 256>>>(w_ih);
    k_gx_mma  <<<dim3(24, 256), 256, GX_SMEM>>>(lab);
    k_scan_tc <<<NCTA, TPB, SCANTC_SMEM>>>(w_hh, b_hh);
    k_logits  <<<Bn * Sn / 64, 256>>>(lab, w_out, b_out, out);
}

// round 7
// speedup vs baseline: 4.0152x; 1.2311x over previous
#include <cuda_runtime.h>
#include <cuda_bf16.h>
#include <math.h>

#define Bn 64
#define Sn 512
#define Hn 1024
#define En 128
#define Ln 49
#define G3 3072            // 3*H
#define IW 1152            // E+H
#define NEGV (-1e12f)

#define NCTA 128
#define TPB  256

// k_gx_mma: 128x128 CTA tile, K staged 64 wide, double buffered
#define GX_SMEM (2 * 2 * 128 * 64 * 2)   // 65536

// k_scan_tc smem: w 48KB + h pair ping-pong 2x32KB + psum 8x64x24 fp32 48KB
#define SCANTC_SMEM (49152 + 65536 + 49152)

// ---------------- device scratch ----------------
__device__ __align__(16) float g_gx[(size_t)Bn * Sn * G3];     // [t][b][3H]
__device__ __align__(16) float g_outs[(size_t)Bn * Sn * Hn];   // [b][t][H]
__device__ __align__(16) float g_lt[Ln * G3];
__device__ __align__(16) __nv_bfloat16 g_hbf[2][Bn * Hn];      // bf16 h ping-pong
__device__ __align__(16) uint4 g_abf[(size_t)Bn * Sn * 128];   // bf16 A [m=t*64+b][1024]
__device__ __align__(16) uint4 g_bbf[(size_t)G3 * 128];        // bf16 B [g][1024]
__device__ unsigned g_grp[8];
__device__ unsigned g_root;
__device__ unsigned g_gen2;

// ---------------- PTX helpers ----------------
__device__ __forceinline__ unsigned smem_u32(const void* p) {
    unsigned a;
    asm("{ .reg .u64 t; cvta.to.shared.u64 t, %1; cvt.u32.u64 %0, t; }" : "=r"(a) : "l"(p));
    return a;
}
__device__ __forceinline__ void ldsm_x4(unsigned* r, unsigned addr) {
    asm volatile("ldmatrix.sync.aligned.m8n8.x4.shared.b16 {%0,%1,%2,%3}, [%4];"
                 : "=r"(r[0]), "=r"(r[1]), "=r"(r[2]), "=r"(r[3]) : "r"(addr));
}
__device__ __forceinline__ void ldsm_x2(unsigned* r, unsigned addr) {
    asm volatile("ldmatrix.sync.aligned.m8n8.x2.shared.b16 {%0,%1}, [%2];"
                 : "=r"(r[0]), "=r"(r[1]) : "r"(addr));
}
__device__ __forceinline__ void mma_bf16(float* c, const unsigned* a, const unsigned* b) {
    asm volatile(
        "mma.sync.aligned.m16n8k16.row.col.f32.bf16.bf16.f32 "
        "{%0,%1,%2,%3}, {%4,%5,%6,%7}, {%8,%9}, {%0,%1,%2,%3};"
        : "+f"(c[0]), "+f"(c[1]), "+f"(c[2]), "+f"(c[3])
        : "r"(a[0]), "r"(a[1]), "r"(a[2]), "r"(a[3]), "r"(b[0]), "r"(b[1]));
}
__device__ __forceinline__ float tanhfast(float x) {
    float y;
    asm("tanh.approx.f32 %0, %1;" : "=f"(y) : "f"(x));
    return y;
}
__device__ __forceinline__ float sigfast(float x) {
    return __fdividef(1.f, 1.f + __expf(-x));
}

// ---------------- two-level grid barrier ----------------
__device__ __forceinline__ void gbar2(int cta) {
    __threadfence();
    __syncthreads();
    if (threadIdx.x == 0) {
        unsigned gen = *((volatile unsigned*)&g_gen2);
        int grp = cta >> 4;
        if (atomicAdd(&g_grp[grp], 1u) == 15u) {
            atomicExch(&g_grp[grp], 0u);
            if (atomicAdd(&g_root, 1u) == 7u) {
                atomicExch(&g_root, 0u);
                __threadfence();
                atomicExch(&g_gen2, gen + 1u);
            }
        }
        while (*((volatile unsigned*)&g_gen2) == gen) {}
        __threadfence();
    }
    __syncthreads();
}

// ---------------- IOBES ----------------
__device__ __forceinline__ bool allowf(int prev, int nxt) {
    if (prev == 0 || ((prev - 1) & 3) >= 2) {
        if (nxt == 0) return true;
        int np = (nxt - 1) & 3;
        return (np == 0) || (np == 3);
    } else {
        if (nxt == 0) return false;
        int np = (nxt - 1) & 3;
        return (((nxt - 1) >> 2) == ((prev - 1) >> 2)) && (np == 1 || np == 2);
    }
}
__device__ __forceinline__ int clamp_lab(int v) {
    return v < 0 ? 0 : (v > Ln - 1 ? Ln - 1 : v);
}

// ---------------- k_lt ----------------
__global__ void k_lt(const float* __restrict__ emb,
                     const float* __restrict__ w_ih,
                     const float* __restrict__ b_ih) {
    int l = blockIdx.y;
    int g = blockIdx.x * 128 + threadIdx.x;
    __shared__ float es[En];
    if (threadIdx.x < En) es[threadIdx.x] = emb[l * En + threadIdx.x];
    __syncthreads();
    float acc = b_ih[g];
    const float* w = w_ih + (size_t)g * IW;
#pragma unroll 8
    for (int e = 0; e < En; e++) acc = fmaf(es[e], w[e], acc);
    g_lt[l * G3 + g] = acc;
}

// ---------------- bf16 cast kernels ----------------
__device__ __forceinline__ unsigned pk2(float a, float b) {
    __nv_bfloat162 h = __floats2bfloat162_rn(a, b);
    return *(unsigned*)&h;
}
__global__ void k_cast_a(const float* __restrict__ we) {
    size_t c = (size_t)blockIdx.x * 256 + threadIdx.x;
    int m = (int)(c >> 7), kq = (int)(c & 127);
    int t = m >> 6, b = m & 63;
    const float4* src = (const float4*)(we + ((size_t)b * Sn + t) * Hn + kq * 8);
    float4 f0 = src[0], f1 = src[1];
    uint4 o;
    o.x = pk2(f0.x, f0.y); o.y = pk2(f0.z, f0.w);
    o.z = pk2(f1.x, f1.y); o.w = pk2(f1.z, f1.w);
    g_abf[c] = o;
}
__global__ void k_cast_b(const float* __restrict__ w_ih) {
    size_t c = (size_t)blockIdx.x * 256 + threadIdx.x;
    int g = (int)(c >> 7), kq = (int)(c & 127);
    const float4* src = (const float4*)(w_ih + (size_t)g * IW + En + kq * 8);
    float4 f0 = src[0], f1 = src[1];
    uint4 o;
    o.x = pk2(f0.x, f0.y); o.y = pk2(f0.z, f0.w);
    o.z = pk2(f1.x, f1.y); o.w = pk2(f1.z, f1.w);
    g_bbf[c] = o;
}

// ---------------- k_gx_mma: HMMA bf16 GEMM + lt epilogue ------------------
__global__ void __launch_bounds__(256, 1) k_gx_mma(const int* __restrict__ lab) {
    extern __shared__ char smem[];
    unsigned sb = smem_u32(smem);
    const unsigned aOff[2] = { 0u, 32768u };
    const unsigned bOff[2] = { 16384u, 49152u };

    int tid = threadIdx.x, lane = tid & 31, wid = tid >> 5;
    int wm = wid >> 2, wn = wid & 3;
    int n0 = blockIdx.x * 128;
    int m0 = blockIdx.y * 128;

    float acc[16][4];
#pragma unroll
    for (int i = 0; i < 16; i++)
#pragma unroll
        for (int j = 0; j < 4; j++) acc[i][j] = 0.f;

    uint4 ra[4], rb[4];
#pragma unroll
    for (int q = 0; q < 4; q++) {
        int idx = tid * 4 + q, r = idx >> 3, i = idx & 7;
        ra[q] = g_abf[(size_t)(m0 + r) * 128 + i];
        rb[q] = g_bbf[(size_t)(n0 + r) * 128 + i];
    }

    int il = lane & 15;
    for (int kc = 0; kc < 16; kc++) {
        int s = kc & 1;
#pragma unroll
        for (int q = 0; q < 4; q++) {
            int idx = tid * 4 + q, r = idx >> 3, i = idx & 7;
            unsigned off = (unsigned)(r * 128 + ((i ^ (r & 7)) << 4));
            *(uint4*)(smem + aOff[s] + off) = ra[q];
            *(uint4*)(smem + bOff[s] + off) = rb[q];
        }
        __syncthreads();
        if (kc + 1 < 16) {
#pragma unroll
            for (int q = 0; q < 4; q++) {
                int idx = tid * 4 + q, r = idx >> 3, i = idx & 7;
                ra[q] = g_abf[(size_t)(m0 + r) * 128 + (kc + 1) * 8 + i];
                rb[q] = g_bbf[(size_t)(n0 + r) * 128 + (kc + 1) * 8 + i];
            }
        }
#pragma unroll
        for (int ks = 0; ks < 4; ks++) {
            unsigned afr[4][4], bfr[4][2];
#pragma unroll
            for (int mt = 0; mt < 4; mt++) {
                int row = wm * 64 + mt * 16 + il;
                int ch = ks * 2 + (lane >> 4);
                ldsm_x4(afr[mt], sb + aOff[s] + row * 128 + ((ch ^ (row & 7)) << 4));
            }
#pragma unroll
            for (int nt = 0; nt < 4; nt++) {
                int row = wn * 32 + nt * 8 + (il & 7);
                int ch = ks * 2 + (il >> 3);
                ldsm_x2(bfr[nt], sb + bOff[s] + row * 128 + ((ch ^ (row & 7)) << 4));
            }
#pragma unroll
            for (int mt = 0; mt < 4; mt++)
#pragma unroll
                for (int nt = 0; nt < 4; nt++)
                    mma_bf16(acc[mt * 4 + nt], afr[mt], bfr[nt]);
        }
        __syncthreads();
    }

    int r_in = lane >> 2, c2 = (lane & 3) * 2;
#pragma unroll
    for (int mt = 0; mt < 4; mt++) {
        int r0 = m0 + wm * 64 + mt * 16 + r_in;
        int r1 = r0 + 8;
        int t0 = r0 >> 6, bb0 = r0 & 63;
        int t1 = r1 >> 6, bb1 = r1 & 63;
        int p0 = (t0 == 0) ? 0 : clamp_lab(lab[bb0 * Sn + t0 - 1]);
        int p1 = (t1 == 0) ? 0 : clamp_lab(lab[bb1 * Sn + t1 - 1]);
        const float* lt0 = g_lt + (size_t)p0 * G3;
        const float* lt1 = g_lt + (size_t)p1 * G3;
        float* o0 = g_gx + (size_t)r0 * G3;
        float* o1 = g_gx + (size_t)r1 * G3;
#pragma unroll
        for (int nt = 0; nt < 4; nt++) {
            int n = n0 + wn * 32 + nt * 8 + c2;
            float* a = acc[mt * 4 + nt];
            float2 v0, v1;
            v0.x = a[0] + lt0[n]; v0.y = a[1] + lt0[n + 1];
            v1.x = a[2] + lt1[n]; v1.y = a[3] + lt1[n + 1];
            *(float2*)(o0 + n) = v0;
            *(float2*)(o1 + n) = v1;
        }
    }
}

// ---------------- k_scan_tc: persistent GRU scan, k-split HMMA ------------
// CTA owns 24 W rows (3 gates x 8 h-cols at c0=cta*8).
// Warp w owns k16 slot w in every 128-col chunk (8 slots x 8 chunks = K 1024),
// computes all 4 m-tiles x 3 n-tiles for that slot -> 8-way psum reduce.
// h staged in 256-col chunk-pairs, ping-pong (4 data syncs/step).
__global__ void __launch_bounds__(TPB, 1) k_scan_tc(const float* __restrict__ w_hh,
                                                    const float* __restrict__ b_hh) {
    extern __shared__ char smem[];
    unsigned sb = smem_u32(smem);
    char* w_sm = smem;                       // bf16 [8 kc][24 j][128], swizzled
    char* h_sm = smem + 49152;               // 2 x [2 sub][64 r][256B], swizzled
    float* psum = (float*)(smem + 49152 + 65536);  // [8 w][64][24]
    __shared__ float bhh_s[24];
    const unsigned sw = sb;
    const unsigned sh0 = sb + 49152;

    int cta = blockIdx.x, tid = threadIdx.x;
    int lane = tid & 31, wid = tid >> 5;
    int c0 = cta * 8;

    // one-time: weights -> bf16 smem (ldmatrix layout)
    for (int cid = tid; cid < 3072; cid += TPB) {
        int j = cid >> 7, kchunk = cid & 127;
        int kc = kchunk >> 4, c16 = kchunk & 15;
        int wrow = (j >> 3) * Hn + c0 + (j & 7);
        const float4* s = (const float4*)(w_hh + (size_t)wrow * Hn + kchunk * 8);
        float4 f0 = s[0], f1 = s[1];
        uint4 o;
        o.x = pk2(f0.x, f0.y); o.y = pk2(f0.z, f0.w);
        o.z = pk2(f1.x, f1.y); o.w = pk2(f1.z, f1.w);
        *(uint4*)(w_sm + kc * 6144 + j * 256 + ((c16 ^ (j & 7)) << 4)) = o;
    }
    if (tid < 24) bhh_s[tid] = b_hh[(tid >> 3) * Hn + c0 + (tid & 7)];

    // zero bf16 h buffer 0
    for (int idx = cta * TPB + tid; idx < Bn * Hn * 2 / 16; idx += NCTA * TPB)
        ((uint4*)g_hbf[0])[idx] = make_uint4(0u, 0u, 0u, 0u);
    gbar2(cta);

    int il = lane & 15;
    int r_in = lane >> 2, cc2 = (lane & 3) * 2;
    int kk = wid;                       // this warp's k16 slot (0..7)

    // epilogue task mapping (fixed per thread across steps)
    int ti[2], tc[2];
    ti[0] = tid >> 3;           tc[0] = tid & 7;
    ti[1] = (tid + TPB) >> 3;   tc[1] = tid & 7;
    float hprev[2] = { 0.f, 0.f };

    // prefetch gx for t=0
    float gxa[2][3];
#pragma unroll
    for (int q = 0; q < 2; q++) {
        const float* gxr = g_gx + (size_t)ti[q] * G3 + c0 + tc[q];
        gxa[q][0] = __ldg(gxr);
        gxa[q][1] = __ldg(gxr + 1024);
        gxa[q][2] = __ldg(gxr + 2048);
    }

    for (int t = 0; t < Sn; t++) {
        const __nv_bfloat16* hb = g_hbf[t & 1];

        float acc[12][4];
#pragma unroll
        for (int i = 0; i < 12; i++)
#pragma unroll
            for (int j = 0; j < 4; j++) acc[i][j] = 0.f;

        // prefetch chunk-pair 0: 64 rows x 256 cols = 2048 uint4, 8 per thread
        uint4 pre[8];
#pragma unroll
        for (int q = 0; q < 8; q++) {
            int idx = q * 256 + tid;
            int r = idx >> 5, u = idx & 31;
            pre[q] = *(const uint4*)(hb + (size_t)r * Hn + u * 8);
        }

        for (int kcp = 0; kcp < 4; kcp++) {
            int s = kcp & 1;
            char* hbuf = h_sm + s * 32768;
#pragma unroll
            for (int q = 0; q < 8; q++) {
                int idx = q * 256 + tid;
                int r = idx >> 5, u = idx & 31;
                int sub = u >> 4, c16 = u & 15;
                *(uint4*)(hbuf + sub * 16384 + r * 256 + ((c16 ^ (r & 7)) << 4)) = pre[q];
            }
            if (kcp + 1 < 4) {
#pragma unroll
                for (int q = 0; q < 8; q++) {
                    int idx = q * 256 + tid;
                    int r = idx >> 5, u = idx & 31;
                    pre[q] = *(const uint4*)(hb + (size_t)r * Hn + (kcp + 1) * 256 + u * 8);
                }
            }
            __syncthreads();
            unsigned shb = sh0 + s * 32768;
#pragma unroll
            for (int sub = 0; sub < 2; sub++) {
                int kc = kcp * 2 + sub;
                unsigned a[4][4];
#pragma unroll
                for (int mt = 0; mt < 4; mt++) {
                    int row = mt * 16 + il;
                    int ch = kk * 2 + (lane >> 4);
                    ldsm_x4(a[mt], shb + sub * 16384 + row * 256 + ((ch ^ (row & 7)) << 4));
                }
                unsigned bfr[3][2];
#pragma unroll
                for (int nt = 0; nt < 3; nt++) {
                    int row = nt * 8 + (il & 7);
                    int ch = kk * 2 + (il >> 3);
                    ldsm_x2(bfr[nt], sw + kc * 6144 + row * 256 + ((ch ^ (row & 7)) << 4));
                }
#pragma unroll
                for (int mt = 0; mt < 4; mt++)
#pragma unroll
                    for (int nt = 0; nt < 3; nt++)
                        mma_bf16(acc[mt * 3 + nt], a[mt], bfr[nt]);
            }
            __syncthreads();
        }

        // write this warp's full 64x24 partial
        float* ps = psum + wid * 1536;
#pragma unroll
        for (int mt = 0; mt < 4; mt++) {
            int mr = mt * 16 + r_in;
#pragma unroll
            for (int nt = 0; nt < 3; nt++) {
                int n = nt * 8 + cc2;
                float* a = acc[mt * 3 + nt];
                *(float2*)(ps + mr * 24 + n)       = make_float2(a[0], a[1]);
                *(float2*)(ps + (mr + 8) * 24 + n) = make_float2(a[2], a[3]);
            }
        }
        __syncthreads();

        // epilogue: 2 tasks/thread, 8-way reduce
        __nv_bfloat16* hbn = g_hbf[(t + 1) & 1];
#pragma unroll
        for (int q = 0; q < 2; q++) {
            int i = ti[q], c = tc[q];
            int gc = c0 + c;
            float ghr = bhh_s[c], ghz = bhh_s[8 + c], ghn = bhh_s[16 + c];
#pragma unroll
            for (int w = 0; w < 8; w++) {
                const float* ps = psum + w * 1536 + i * 24;
                ghr += ps[c];
                ghz += ps[8 + c];
                ghn += ps[16 + c];
            }
            float r = sigfast(gxa[q][0] + ghr);
            float z = sigfast(gxa[q][1] + ghz);
            float n = tanhfast(gxa[q][2] + r * ghn);
            float hnew = (1.f - z) * n + z * hprev[q];
            hprev[q] = hnew;
            g_outs[(size_t)i * (Sn * Hn) + (size_t)t * Hn + gc] = hnew;
            hbn[i * Hn + gc] = __float2bfloat16(hnew);
        }

        // prefetch gx for t+1 (hidden under the barrier)
        if (t + 1 < Sn) {
            const float* gxt = g_gx + (size_t)(t + 1) * (Bn * G3);
#pragma unroll
            for (int q = 0; q < 2; q++) {
                const float* gxr = gxt + (size_t)ti[q] * G3 + c0 + tc[q];
                gxa[q][0] = __ldg(gxr);
                gxa[q][1] = __ldg(gxr + 1024);
                gxa[q][2] = __ldg(gxr + 2048);
            }
        }
        gbar2(cta);
    }
}

// ---------------- k_logits ----------------
__global__ void __launch_bounds__(256) k_logits(const int* __restrict__ lab,
                                                const float* __restrict__ w_out,
                                                const float* __restrict__ b_out,
                                                float* __restrict__ out) {
    __shared__ float a_sm[16][68];
    __shared__ float b_sm[16][64];
    int m0 = blockIdx.x * 64;
    int tid = threadIdx.x;

    int ar = tid >> 2, akq = tid & 3;
    int bl = tid & 63, bkq = tid >> 6;
    const float* aptr = g_outs + (size_t)(m0 + ar) * Hn + akq * 4;
    int ty = tid >> 4, tx = tid & 15;

    float acc[4][4];
#pragma unroll
    for (int q = 0; q < 4; q++)
#pragma unroll
        for (int p = 0; p < 4; p++) acc[q][p] = 0.f;

    float4 av = *(const float4*)(aptr);
    float4 bv = make_float4(0.f, 0.f, 0.f, 0.f);
    if (bl < Ln) bv = *(const float4*)(w_out + (size_t)bl * Hn + bkq * 4);

    for (int k0 = 0; k0 < Hn; k0 += 16) {
        a_sm[akq * 4 + 0][ar] = av.x;
        a_sm[akq * 4 + 1][ar] = av.y;
        a_sm[akq * 4 + 2][ar] = av.z;
        a_sm[akq * 4 + 3][ar] = av.w;
        b_sm[bkq * 4 + 0][bl] = bv.x;
        b_sm[bkq * 4 + 1][bl] = bv.y;
        b_sm[bkq * 4 + 2][bl] = bv.z;
        b_sm[bkq * 4 + 3][bl] = bv.w;
        __syncthreads();
        if (k0 + 16 < Hn) {
            av = *(const float4*)(aptr + k0 + 16);
            if (bl < Ln) bv = *(const float4*)(w_out + (size_t)bl * Hn + bkq * 4 + k0 + 16);
        }
#pragma unroll
        for (int kk = 0; kk < 16; kk++) {
            float4 a4 = *(const float4*)&a_sm[kk][ty * 4];
            float4 b4 = *(const float4*)&b_sm[kk][tx * 4];
#pragma unroll
            for (int q = 0; q < 4; q++) {
                float aval = (q == 0) ? a4.x : (q == 1) ? a4.y : (q == 2) ? a4.z : a4.w;
                acc[q][0] = fmaf(aval, b4.x, acc[q][0]);
                acc[q][1] = fmaf(aval, b4.y, acc[q][1]);
                acc[q][2] = fmaf(aval, b4.z, acc[q][2]);
                acc[q][3] = fmaf(aval, b4.w, acc[q][3]);
            }
        }
        __syncthreads();
    }

#pragma unroll
    for (int q = 0; q < 4; q++) {
        int row = m0 + ty * 4 + q;
        int b = row >> 9, t = row & 511;
        int prev = (t == 0) ? 0 : clamp_lab(lab[b * Sn + t - 1]);
#pragma unroll
        for (int p = 0; p < 4; p++) {
            int l = tx * 4 + p;
            if (l < Ln) {
                float v = allowf(prev, l) ? (acc[q][p] + b_out[l]) : NEGV;
                out[(size_t)row * Ln + l] = v;
            }
        }
    }
}

// ---------------- launcher ----------------
extern "C" void kernel_launch(void* const* d_in, const int* in_sizes, int n_in,
                              void* d_out, int out_size) {
    const float* we    = nullptr;
    const int*   lab   = nullptr;
    const float* emb   = nullptr;
    const float* w_ih  = nullptr;
    const float* w_hh  = nullptr;
    const float* b_ih  = nullptr;
    const float* b_hh  = nullptr;
    const float* w_out = nullptr;
    const float* b_out = nullptr;

    for (int i = 0; i < n_in; i++) {
        int n = in_sizes[i];
        const void* p = d_in[i];
        switch (n) {
            case 33554432: we    = (const float*)p; break;
            case 32768:    lab   = (const int*)p;   break;
            case 6272:     emb   = (const float*)p; break;
            case 3538944:  w_ih  = (const float*)p; break;
            case 3145728:  w_hh  = (const float*)p; break;
            case 50176:    w_out = (const float*)p; break;
            case 49:       b_out = (const float*)p; break;
            case 3072:
                if (!b_ih) b_ih = (const float*)p; else b_hh = (const float*)p;
                break;
            default: break;
        }
    }
    float* out = (float*)d_out;

    cudaFuncSetAttribute(k_gx_mma,  cudaFuncAttributeMaxDynamicSharedMemorySize, GX_SMEM);
    cudaFuncSetAttribute(k_scan_tc, cudaFuncAttributeMaxDynamicSharedMemorySize, SCANTC_SMEM);

    k_lt      <<<dim3(24, Ln), 128>>>(emb, w_ih, b_ih);
    k_cast_a  <<<16384, 256>>>(we);
    k_cast_b  <<<1536, 256>>>(w_ih);
    k_gx_mma  <<<dim3(24, 256), 256, GX_SMEM>>>(lab);
    k_scan_tc <<<NCTA, TPB, SCANTC_SMEM>>>(w_hh, b_hh);
    k_logits  <<<Bn * Sn / 64, 256>>>(lab, w_out, b_out, out);
}